// round 2
// baseline (speedup 1.0000x reference)
#include <cuda_runtime.h>
#include <cstdint>

#define SEQL  128
#define BATCH 64
#define EMB   512
#define HID   1024
#define VOCAB 32000
#define G4    4096      // 4*HID
#define MTOT  8192      // SEQL*BATCH

// ---------------- scratch (device globals: sanctioned, no runtime alloc) ----
__device__ __align__(128) float g_xg[(size_t)MTOT * G4];     // 134 MB
__device__ __align__(128) float g_hid[(size_t)MTOT * HID];   // 33.5 MB
__device__ __align__(128) float g_WihT[(size_t)G4 * EMB];    // 8 MB
__device__ __align__(128) float g_WhhT[(size_t)G4 * HID];    // 16 MB
__device__ __align__(128) float g_c[BATCH * HID];
__device__ int g_bar[SEQL];

// ---------------- helpers ---------------------------------------------------
__device__ __forceinline__ uint32_t f2tf32(float x) {
    uint32_t u;
    asm("cvt.rna.tf32.f32 %0, %1;" : "=r"(u) : "f"(x));
    return u;
}

__device__ __forceinline__ void mma8(float* d, const uint32_t* a, const uint32_t* b) {
    asm volatile(
        "mma.sync.aligned.m16n8k8.row.col.f32.tf32.tf32.f32 "
        "{%0,%1,%2,%3}, {%4,%5,%6,%7}, {%8,%9}, {%0,%1,%2,%3};"
        : "+f"(d[0]), "+f"(d[1]), "+f"(d[2]), "+f"(d[3])
        : "r"(a[0]), "r"(a[1]), "r"(a[2]), "r"(a[3]), "r"(b[0]), "r"(b[1]));
}

__device__ __forceinline__ float sigmoidf_(float x) {
    return 1.0f / (1.0f + __expf(-x));
}

// ---------------- init / transpose / tail -----------------------------------
__global__ void init_k(const float* __restrict__ c0) {
    int i = blockIdx.x * blockDim.x + threadIdx.x;
    if (i < BATCH * HID) g_c[i] = c0[i];
    if (i < SEQL) g_bar[i] = 0;
}

// in: R x C row-major -> out: C x R row-major. which: 0->g_WihT, 1->g_WhhT
__global__ void transpose_k(const float* __restrict__ in, int R, int C, int which) {
    __shared__ float tmp[32][33];
    float* out = which ? g_WhhT : g_WihT;
    int cb = blockIdx.x << 5, rb = blockIdx.y << 5;
    int x = threadIdx.x, y = threadIdx.y;
#pragma unroll
    for (int i = 0; i < 32; i += 8)
        tmp[y + i][x] = in[(size_t)(rb + y + i) * C + cb + x];
    __syncthreads();
#pragma unroll
    for (int i = 0; i < 32; i += 8)
        out[(size_t)(cb + y + i) * R + rb + x] = tmp[x][y + i];
}

__global__ void tail_k(float* __restrict__ out) {
    int i = blockIdx.x * blockDim.x + threadIdx.x;
    if (i < BATCH * HID) {
        const size_t LOG = (size_t)MTOT * VOCAB;
        out[LOG + i] = g_hid[(size_t)(SEQL - 1) * BATCH * HID + i];
        out[LOG + (size_t)BATCH * HID + i] = g_c[i];
    }
}

// ---------------- generic tf32 GEMM:  C = A(MxK) @ B^T(NxK) + bias ----------
// A row-major with row gather (gidx) or direct; B is N x K row-major.
// BM=BN=128, BK=32, 256 threads (8 warps as 2m x 4n, warp tile 64x32).
__global__ __launch_bounds__(256, 2)
void gemm_tf32(const float* __restrict__ A, const float* __restrict__ B,
               float* __restrict__ C, const float* __restrict__ bias,
               const int* __restrict__ gidx,
               int M, int N, int K, int lda, int GROUPM)
{
    __shared__ uint32_t As[128][36];
    __shared__ uint32_t Bs[128][36];
    __shared__ int sidx[128];

    const int grid_m = M >> 7, grid_n = N >> 7;
    const int pid = blockIdx.x;
    const int width = GROUPM * grid_n;
    const int grp = pid / width;
    const int first = grp * GROUPM;
    const int gsz = min(grid_m - first, GROUPM);
    const int pm = first + (pid % width) % gsz;
    const int pn = (pid % width) / gsz;
    const int m0 = pm << 7, n0 = pn << 7;

    const int tid = threadIdx.x, lane = tid & 31, wid = tid >> 5;
    const int wm = (wid & 1) << 6;   // 0 or 64
    const int wn = (wid >> 1) << 5;  // 0..96

    if (tid < 128) sidx[tid] = gidx ? gidx[m0 + tid] : (m0 + tid);
    __syncthreads();

    float acc[4][4][4];
#pragma unroll
    for (int i = 0; i < 4; i++)
#pragma unroll
        for (int j = 0; j < 4; j++)
#pragma unroll
            for (int q = 0; q < 4; q++) acc[i][j][q] = 0.f;

    for (int kt = 0; kt < K; kt += 32) {
#pragma unroll
        for (int i = 0; i < 4; i++) {
            int l = tid + (i << 8);
            int r = l >> 3, kq = (l & 7) << 2;
            float4 v = *(const float4*)(A + (size_t)sidx[r] * lda + kt + kq);
            As[r][kq]     = f2tf32(v.x);
            As[r][kq + 1] = f2tf32(v.y);
            As[r][kq + 2] = f2tf32(v.z);
            As[r][kq + 3] = f2tf32(v.w);
        }
#pragma unroll
        for (int i = 0; i < 4; i++) {
            int l = tid + (i << 8);
            int r = l >> 3, kq = (l & 7) << 2;
            float4 v = *(const float4*)(B + (size_t)(n0 + r) * K + kt + kq);
            Bs[r][kq]     = f2tf32(v.x);
            Bs[r][kq + 1] = f2tf32(v.y);
            Bs[r][kq + 2] = f2tf32(v.z);
            Bs[r][kq + 3] = f2tf32(v.w);
        }
        __syncthreads();
#pragma unroll
        for (int ks = 0; ks < 4; ks++) {
            const int k0 = ks << 3;
            uint32_t af[4][4], bf[4][2];
#pragma unroll
            for (int fm = 0; fm < 4; fm++) {
                int r = wm + (fm << 4) + (lane >> 2);
                af[fm][0] = As[r][k0 + (lane & 3)];
                af[fm][1] = As[r + 8][k0 + (lane & 3)];
                af[fm][2] = As[r][k0 + (lane & 3) + 4];
                af[fm][3] = As[r + 8][k0 + (lane & 3) + 4];
            }
#pragma unroll
            for (int fn = 0; fn < 4; fn++) {
                int c = wn + (fn << 3) + (lane >> 2);
                bf[fn][0] = Bs[c][k0 + (lane & 3)];
                bf[fn][1] = Bs[c][k0 + (lane & 3) + 4];
            }
#pragma unroll
            for (int fm = 0; fm < 4; fm++)
#pragma unroll
                for (int fn = 0; fn < 4; fn++)
                    mma8(acc[fm][fn], af[fm], bf[fn]);
        }
        __syncthreads();
    }

#pragma unroll
    for (int fm = 0; fm < 4; fm++) {
        int r = m0 + wm + (fm << 4) + (lane >> 2);
#pragma unroll
        for (int fn = 0; fn < 4; fn++) {
            int c = n0 + wn + (fn << 3) + ((lane & 3) << 1);
            float b0 = bias[c], b1 = bias[c + 1];
            float2 v0 = make_float2(acc[fm][fn][0] + b0, acc[fm][fn][1] + b1);
            float2 v1 = make_float2(acc[fm][fn][2] + b0, acc[fm][fn][3] + b1);
            *(float2*)(C + (size_t)r * N + c) = v0;
            *(float2*)(C + (size_t)(r + 8) * N + c) = v1;
        }
    }
}

// ---------------- persistent LSTM recurrence --------------------------------
// 64 blocks x 128 threads. Block b owns hidden units [16b,16b+16) and all 4
// gates for them: a 64(batch) x 64(4 gates x 16 units) tile of gates per step.
// gates = xg[t] + h_{t-1} @ W_hh  (B from pre-transposed g_WhhT).
// Global software barrier (per-step counters) between steps.
__global__ __launch_bounds__(128, 1)
void lstm_rec(const float* __restrict__ h0_in)
{
    __shared__ uint32_t As[64][36];
    __shared__ uint32_t Bs[64][36];
    __shared__ float Gs[64][68];

    const int tid = threadIdx.x, lane = tid & 31, wid = tid >> 5;
    const int u0 = blockIdx.x << 4;

    for (int t = 0; t < SEQL; t++) {
        const float* hprev = (t == 0) ? h0_in
                                      : (g_hid + (size_t)(t - 1) * BATCH * HID);
        float acc[4][2][4];
#pragma unroll
        for (int i = 0; i < 4; i++)
#pragma unroll
            for (int j = 0; j < 2; j++)
#pragma unroll
                for (int q = 0; q < 4; q++) acc[i][j][q] = 0.f;

        for (int kt = 0; kt < HID; kt += 32) {
#pragma unroll
            for (int i = 0; i < 4; i++) {
                int l = tid + (i << 7);
                int r = l >> 3, kq = (l & 7) << 2;
                float4 v = *(const float4*)(hprev + (size_t)r * HID + kt + kq);
                As[r][kq]     = f2tf32(v.x);
                As[r][kq + 1] = f2tf32(v.y);
                As[r][kq + 2] = f2tf32(v.z);
                As[r][kq + 3] = f2tf32(v.w);
            }
#pragma unroll
            for (int i = 0; i < 4; i++) {
                int l = tid + (i << 7);
                int r = l >> 3, kq = (l & 7) << 2;
                int brow = ((r >> 4) << 10) + u0 + (r & 15);  // gate*HID + unit
                float4 v = *(const float4*)(g_WhhT + (size_t)brow * HID + kt + kq);
                Bs[r][kq]     = f2tf32(v.x);
                Bs[r][kq + 1] = f2tf32(v.y);
                Bs[r][kq + 2] = f2tf32(v.z);
                Bs[r][kq + 3] = f2tf32(v.w);
            }
            __syncthreads();
#pragma unroll
            for (int ks = 0; ks < 4; ks++) {
                const int k0 = ks << 3;
                uint32_t af[4][4], bf[2][2];
#pragma unroll
                for (int fm = 0; fm < 4; fm++) {
                    int r = (fm << 4) + (lane >> 2);
                    af[fm][0] = As[r][k0 + (lane & 3)];
                    af[fm][1] = As[r + 8][k0 + (lane & 3)];
                    af[fm][2] = As[r][k0 + (lane & 3) + 4];
                    af[fm][3] = As[r + 8][k0 + (lane & 3) + 4];
                }
#pragma unroll
                for (int fn = 0; fn < 2; fn++) {
                    int c = (wid << 4) + (fn << 3) + (lane >> 2);
                    bf[fn][0] = Bs[c][k0 + (lane & 3)];
                    bf[fn][1] = Bs[c][k0 + (lane & 3) + 4];
                }
#pragma unroll
                for (int fm = 0; fm < 4; fm++)
#pragma unroll
                    for (int fn = 0; fn < 2; fn++)
                        mma8(acc[fm][fn], af[fm], bf[fn]);
            }
            __syncthreads();
        }

        // spill gate tile to smem so pointwise sees all 4 gates per unit
#pragma unroll
        for (int fm = 0; fm < 4; fm++) {
            int r = (fm << 4) + (lane >> 2);
#pragma unroll
            for (int fn = 0; fn < 2; fn++) {
                int c = (wid << 4) + (fn << 3) + ((lane & 3) << 1);
                Gs[r][c]         = acc[fm][fn][0];
                Gs[r][c + 1]     = acc[fm][fn][1];
                Gs[r + 8][c]     = acc[fm][fn][2];
                Gs[r + 8][c + 1] = acc[fm][fn][3];
            }
        }
        __syncthreads();

        // pointwise: 64 batch x 16 units = 1024 elems / 128 threads
#pragma unroll
        for (int i = 0; i < 8; i++) {
            int p = tid + (i << 7);
            int row = p >> 4, u = p & 15;
            size_t xb = ((size_t)(t * BATCH + row)) * G4 + u0 + u;
            float gi = Gs[row][u]      + g_xg[xb];
            float gf = Gs[row][16 + u] + g_xg[xb + HID];
            float gg = Gs[row][32 + u] + g_xg[xb + 2 * HID];
            float go = Gs[row][48 + u] + g_xg[xb + 3 * HID];
            float iv = sigmoidf_(gi);
            float fv = sigmoidf_(gf);
            float gv = tanhf(gg);
            float ov = sigmoidf_(go);
            int ci = row * HID + u0 + u;
            float cv = fv * g_c[ci] + iv * gv;
            g_c[ci] = cv;
            g_hid[(size_t)(t * BATCH + row) * HID + u0 + u] = ov * tanhf(cv);
        }

        // global barrier: all 64 blocks finish step t before step t+1
        __threadfence();
        __syncthreads();
        if (tid == 0) {
            atomicAdd(&g_bar[t], 1);
            while (*(volatile int*)&g_bar[t] < 64) __nanosleep(64);
        }
        __syncthreads();
    }
}

// ---------------- launch -----------------------------------------------------
extern "C" void kernel_launch(void* const* d_in, const int* in_sizes, int n_in,
                              void* d_out, int out_size)
{
    const int*   input  = (const int*)d_in[0];
    const float* emb    = (const float*)d_in[1];
    const float* W_ih   = (const float*)d_in[2];
    const float* W_hh   = (const float*)d_in[3];
    const float* b_lstm = (const float*)d_in[4];
    const float* lin_W  = (const float*)d_in[5];
    const float* lin_b  = (const float*)d_in[6];
    const float* h0     = (const float*)d_in[7];
    const float* c0     = (const float*)d_in[8];
    float* out = (float*)d_out;

    float *p_xg, *p_hid, *p_wihT;
    cudaGetSymbolAddress((void**)&p_xg, g_xg);
    cudaGetSymbolAddress((void**)&p_hid, g_hid);
    cudaGetSymbolAddress((void**)&p_wihT, g_WihT);

    transpose_k<<<dim3(G4 / 32, EMB / 32), dim3(32, 8)>>>(W_ih, EMB, G4, 0);
    transpose_k<<<dim3(G4 / 32, HID / 32), dim3(32, 8)>>>(W_hh, HID, G4, 1);
    init_k<<<(BATCH * HID + 255) / 256, 256>>>(c0);

    // Phase 1: xg = gather(emb, input) @ W_ih + b_lstm   (M=8192,N=4096,K=512)
    gemm_tf32<<<(MTOT / 128) * (G4 / 128), 256>>>(
        emb, p_wihT, p_xg, b_lstm, input, MTOT, G4, EMB, EMB, 16);

    // Phase 2: 128 LSTM steps, persistent kernel
    lstm_rec<<<64, 128>>>(h0);

    // Phase 3: logits = hidden @ lin_W^T + lin_b   (M=8192,N=32000,K=1024)
    gemm_tf32<<<(MTOT / 128) * (VOCAB / 128), 256>>>(
        p_hid, lin_W, out, lin_b, nullptr, MTOT, VOCAB, HID, HID, 16);

    // Phase 4: append h_T, c_T after logits
    tail_k<<<(BATCH * HID + 255) / 256, 256>>>(out);
}

// round 3
// speedup vs baseline: 2.0322x; 2.0322x over previous
#include <cuda_runtime.h>
#include <cstdint>

#define SEQL  128
#define BATCH 64
#define EMB   512
#define HID   1024
#define VOCAB 32000
#define G4    4096      // 4*HID
#define MTOT  8192      // SEQL*BATCH

// ---------------- scratch (device globals: sanctioned, no runtime alloc) ----
__device__ __align__(128) float g_xg[(size_t)MTOT * G4];     // 134 MB
__device__ __align__(128) float g_hid[(size_t)MTOT * HID];   // 33.5 MB
__device__ __align__(128) float g_WihT[(size_t)G4 * EMB];    // 8 MB
__device__ __align__(128) float g_WhhT[(size_t)G4 * HID];    // 16 MB
__device__ __align__(128) float g_c[BATCH * HID];
__device__ int g_bar[SEQL];

// ---------------- helpers ---------------------------------------------------
__device__ __forceinline__ uint32_t f2tf32(float x) {
    uint32_t u;
    asm("cvt.rna.tf32.f32 %0, %1;" : "=r"(u) : "f"(x));
    return u;
}

__device__ __forceinline__ void mma8(float* d, const uint32_t* a, const uint32_t* b) {
    asm volatile(
        "mma.sync.aligned.m16n8k8.row.col.f32.tf32.tf32.f32 "
        "{%0,%1,%2,%3}, {%4,%5,%6,%7}, {%8,%9}, {%0,%1,%2,%3};"
        : "+f"(d[0]), "+f"(d[1]), "+f"(d[2]), "+f"(d[3])
        : "r"(a[0]), "r"(a[1]), "r"(a[2]), "r"(a[3]), "r"(b[0]), "r"(b[1]));
}

__device__ __forceinline__ float sigmoidf_(float x) {
    return 1.0f / (1.0f + __expf(-x));
}

__device__ __forceinline__ void cp16(uint32_t dst, const void* src) {
    asm volatile("cp.async.ca.shared.global [%0], [%1], 16;" :: "r"(dst), "l"(src));
}
__device__ __forceinline__ void cp_commit() {
    asm volatile("cp.async.commit_group;");
}
template <int N>
__device__ __forceinline__ void cp_wait() {
    asm volatile("cp.async.wait_group %0;" :: "n"(N));
}

// ---------------- init / transpose / tail -----------------------------------
__global__ void init_k(const float* __restrict__ c0) {
    int i = blockIdx.x * blockDim.x + threadIdx.x;
    if (i < BATCH * HID) g_c[i] = c0[i];
    if (i < SEQL) g_bar[i] = 0;
}

// in: R x C row-major -> out: C x R row-major. which: 0->g_WihT, 1->g_WhhT
__global__ void transpose_k(const float* __restrict__ in, int R, int C, int which) {
    __shared__ float tmp[32][33];
    float* out = which ? g_WhhT : g_WihT;
    int cb = blockIdx.x << 5, rb = blockIdx.y << 5;
    int x = threadIdx.x, y = threadIdx.y;
#pragma unroll
    for (int i = 0; i < 32; i += 8)
        tmp[y + i][x] = in[(size_t)(rb + y + i) * C + cb + x];
    __syncthreads();
#pragma unroll
    for (int i = 0; i < 32; i += 8)
        out[(size_t)(cb + y + i) * R + rb + x] = tmp[x][y + i];
}

__global__ void tail_k(float* __restrict__ out) {
    int i = blockIdx.x * blockDim.x + threadIdx.x;
    if (i < BATCH * HID) {
        const size_t LOG = (size_t)MTOT * VOCAB;
        out[LOG + i] = g_hid[(size_t)(SEQL - 1) * BATCH * HID + i];
        out[LOG + (size_t)BATCH * HID + i] = g_c[i];
    }
}

// ---------------- pipelined tf32 GEMM:  C = A(MxK) @ B^T(NxK) + bias --------
// A row-major with optional row gather; B is N x K row-major.
// BM=BN=128, BK=32, 256 threads, 3-stage cp.async pipeline.
// smem: 3 stages x (As 128x36 + Bs 128x36) floats = 110592 B (dynamic).
#define GSTG 4608   // floats per (As or Bs) stage = 128*36
__global__ __launch_bounds__(256, 2)
void gemm_tf32p(const float* __restrict__ A, const float* __restrict__ B,
                float* __restrict__ C, const float* __restrict__ bias,
                const int* __restrict__ gidx,
                int M, int N, int K, int lda, int GROUPM)
{
    extern __shared__ float dsm[];
    float* Asm = dsm;               // [3][128][36]
    float* Bsm = dsm + 3 * GSTG;    // [3][128][36]
    __shared__ int sidx[128];

    const int grid_m = M >> 7, grid_n = N >> 7;
    const int pid = blockIdx.x;
    const int width = GROUPM * grid_n;
    const int grp = pid / width;
    const int first = grp * GROUPM;
    const int gsz = min(grid_m - first, GROUPM);
    const int pm = first + (pid % width) % gsz;
    const int pn = (pid % width) / gsz;
    const int m0 = pm << 7, n0 = pn << 7;

    const int tid = threadIdx.x, lane = tid & 31, wid = tid >> 5;
    const int wm = (wid & 1) << 6;
    const int wn = (wid >> 1) << 5;

    if (tid < 128) sidx[tid] = gidx ? gidx[m0 + tid] : (m0 + tid);
    __syncthreads();

    const uint32_t asb = (uint32_t)__cvta_generic_to_shared(Asm);
    const uint32_t bsb = (uint32_t)__cvta_generic_to_shared(Bsm);

    const int NK = K >> 5;

    auto load_stage = [&](int st, int kt) {
#pragma unroll
        for (int i = 0; i < 4; i++) {
            int l = tid + (i << 8);
            int r = l >> 3, kq = (l & 7) << 2;
            cp16(asb + (uint32_t)(st * GSTG + r * 36 + kq) * 4,
                 A + (size_t)sidx[r] * lda + kt + kq);
            cp16(bsb + (uint32_t)(st * GSTG + r * 36 + kq) * 4,
                 B + (size_t)(n0 + r) * K + kt + kq);
        }
    };

    float acc[4][4][4];
#pragma unroll
    for (int i = 0; i < 4; i++)
#pragma unroll
        for (int j = 0; j < 4; j++)
#pragma unroll
            for (int q = 0; q < 4; q++) acc[i][j][q] = 0.f;

    load_stage(0, 0); cp_commit();
    load_stage(1, 32); cp_commit();

    for (int it = 0; it < NK; it++) {
        if (it + 2 < NK) load_stage((it + 2) % 3, (it + 2) << 5);
        cp_commit();            // group committed even when empty
        cp_wait<2>();           // stage it%3 resident
        __syncthreads();

        const float* Ab = Asm + (it % 3) * GSTG;
        const float* Bb = Bsm + (it % 3) * GSTG;
#pragma unroll
        for (int ks = 0; ks < 4; ks++) {
            const int k0 = ks << 3;
            uint32_t af[4][4], bf[4][2];
#pragma unroll
            for (int fm = 0; fm < 4; fm++) {
                int r = wm + (fm << 4) + (lane >> 2);
                af[fm][0] = f2tf32(Ab[r * 36 + k0 + (lane & 3)]);
                af[fm][1] = f2tf32(Ab[(r + 8) * 36 + k0 + (lane & 3)]);
                af[fm][2] = f2tf32(Ab[r * 36 + k0 + (lane & 3) + 4]);
                af[fm][3] = f2tf32(Ab[(r + 8) * 36 + k0 + (lane & 3) + 4]);
            }
#pragma unroll
            for (int fn = 0; fn < 4; fn++) {
                int c = wn + (fn << 3) + (lane >> 2);
                bf[fn][0] = f2tf32(Bb[c * 36 + k0 + (lane & 3)]);
                bf[fn][1] = f2tf32(Bb[c * 36 + k0 + (lane & 3) + 4]);
            }
#pragma unroll
            for (int fm = 0; fm < 4; fm++)
#pragma unroll
                for (int fn = 0; fn < 4; fn++)
                    mma8(acc[fm][fn], af[fm], bf[fn]);
        }
        __syncthreads();
    }

#pragma unroll
    for (int fm = 0; fm < 4; fm++) {
        int r = m0 + wm + (fm << 4) + (lane >> 2);
#pragma unroll
        for (int fn = 0; fn < 4; fn++) {
            int c = n0 + wn + (fn << 3) + ((lane & 3) << 1);
            float b0 = bias[c], b1 = bias[c + 1];
            float2 v0 = make_float2(acc[fm][fn][0] + b0, acc[fm][fn][1] + b1);
            float2 v1 = make_float2(acc[fm][fn][2] + b0, acc[fm][fn][3] + b1);
            *(float2*)(C + (size_t)r * N + c) = v0;
            *(float2*)(C + (size_t)(r + 8) * N + c) = v1;
        }
    }
}

// ---------------- persistent LSTM recurrence --------------------------------
// 128 blocks x 128 threads. Block b owns 8 hidden units [8b, 8b+8) and all 4
// gates -> 32 gate-rows of W_hh, which live PRE-CONVERTED (tf32) in SMEM for
// all 128 steps (32 x 1024, stride 1028 => conflict-free fragment loads).
// Per step: gates = xg[t] + h_{t-1} @ W_hh_slice, h tile double-buffered via
// cp.async. Software global barrier between steps.
#define LSTG 2304   // floats per A stage = 64*36
__global__ __launch_bounds__(128, 1)
void lstm_rec2(const float* __restrict__ h0_in)
{
    extern __shared__ uint32_t dsmu[];
    uint32_t* Bw = dsmu;                              // 32 x 1028 tf32
    float* Asm = (float*)(dsmu + 32 * 1028);          // [2][64][36]
    float* Gs  = Asm + 2 * LSTG;                      // [64][36]

    const int tid = threadIdx.x, lane = tid & 31, wid = tid >> 5;
    const int u0 = blockIdx.x << 3;                   // 8 units per block

    // Load this block's W_hh slice once, pre-converted to tf32.
    for (int idx = tid; idx < 32 * 1024; idx += 128) {
        int r = idx >> 10, k = idx & 1023;
        int grow = ((r >> 3) << 10) + u0 + (r & 7);   // gate*HID + unit
        Bw[r * 1028 + k] = f2tf32(g_WhhT[(size_t)grow * HID + k]);
    }
    __syncthreads();

    const uint32_t asb = (uint32_t)__cvta_generic_to_shared(Asm);

    for (int t = 0; t < SEQL; t++) {
        const float* hprev = t ? (g_hid + (size_t)(t - 1) * BATCH * HID) : h0_in;

        float acc[4][4];
#pragma unroll
        for (int i = 0; i < 4; i++)
#pragma unroll
            for (int q = 0; q < 4; q++) acc[i][q] = 0.f;

        auto loadA = [&](int st, int kt) {
#pragma unroll
            for (int i = 0; i < 4; i++) {
                int l = tid + (i << 7);
                int r = l >> 3, kq = (l & 7) << 2;
                cp16(asb + (uint32_t)(st * LSTG + r * 36 + kq) * 4,
                     hprev + (size_t)r * HID + kt + kq);
            }
        };

        loadA(0, 0); cp_commit();
        for (int it = 0; it < 32; it++) {
            if (it + 1 < 32) { loadA((it + 1) & 1, (it + 1) << 5); cp_commit(); cp_wait<1>(); }
            else              cp_wait<0>();
            __syncthreads();

            const float* Ab = Asm + (it & 1) * LSTG;
            const int kb = it << 5;
#pragma unroll
            for (int ks = 0; ks < 4; ks++) {
                const int k0 = ks << 3;
                uint32_t af[4][4], bf[2];
#pragma unroll
                for (int fm = 0; fm < 4; fm++) {
                    int r = (fm << 4) + (lane >> 2);
                    af[fm][0] = f2tf32(Ab[r * 36 + k0 + (lane & 3)]);
                    af[fm][1] = f2tf32(Ab[(r + 8) * 36 + k0 + (lane & 3)]);
                    af[fm][2] = f2tf32(Ab[r * 36 + k0 + (lane & 3) + 4]);
                    af[fm][3] = f2tf32(Ab[(r + 8) * 36 + k0 + (lane & 3) + 4]);
                }
                int c = (wid << 3) + (lane >> 2);
                bf[0] = Bw[c * 1028 + kb + k0 + (lane & 3)];
                bf[1] = Bw[c * 1028 + kb + k0 + (lane & 3) + 4];
#pragma unroll
                for (int fm = 0; fm < 4; fm++) mma8(acc[fm], af[fm], bf);
            }
            __syncthreads();
        }

        // spill gate tile (64 batch x 32 gate-cols) to smem
#pragma unroll
        for (int fm = 0; fm < 4; fm++) {
            int r = (fm << 4) + (lane >> 2);
            int c = (wid << 3) + ((lane & 3) << 1);
            Gs[r * 36 + c]           = acc[fm][0];
            Gs[r * 36 + c + 1]       = acc[fm][1];
            Gs[(r + 8) * 36 + c]     = acc[fm][2];
            Gs[(r + 8) * 36 + c + 1] = acc[fm][3];
        }
        __syncthreads();

        // pointwise: 64 batch x 8 units = 512 elems / 128 threads
#pragma unroll
        for (int i = 0; i < 4; i++) {
            int p = tid + (i << 7);
            int row = p >> 3, u = p & 7;
            size_t xb = ((size_t)(t * BATCH + row)) * G4 + u0 + u;
            float gi = Gs[row * 36 + u]      + g_xg[xb];
            float gf = Gs[row * 36 + 8 + u]  + g_xg[xb + HID];
            float gg = Gs[row * 36 + 16 + u] + g_xg[xb + 2 * HID];
            float go = Gs[row * 36 + 24 + u] + g_xg[xb + 3 * HID];
            float iv = sigmoidf_(gi);
            float fv = sigmoidf_(gf);
            float gv = tanhf(gg);
            float ov = sigmoidf_(go);
            int ci = row * HID + u0 + u;
            float cv = fv * g_c[ci] + iv * gv;
            g_c[ci] = cv;
            g_hid[(size_t)(t * BATCH + row) * HID + u0 + u] = ov * tanhf(cv);
        }

        // global barrier: all 128 blocks finish step t before step t+1
        __threadfence();
        __syncthreads();
        if (tid == 0) {
            atomicAdd(&g_bar[t], 1);
            while (*(volatile int*)&g_bar[t] < 128) __nanosleep(32);
        }
        __syncthreads();
    }
}

// ---------------- launch -----------------------------------------------------
extern "C" void kernel_launch(void* const* d_in, const int* in_sizes, int n_in,
                              void* d_out, int out_size)
{
    const int*   input  = (const int*)d_in[0];
    const float* emb    = (const float*)d_in[1];
    const float* W_ih   = (const float*)d_in[2];
    const float* W_hh   = (const float*)d_in[3];
    const float* b_lstm = (const float*)d_in[4];
    const float* lin_W  = (const float*)d_in[5];
    const float* lin_b  = (const float*)d_in[6];
    const float* h0     = (const float*)d_in[7];
    const float* c0     = (const float*)d_in[8];
    float* out = (float*)d_out;

    float *p_xg, *p_hid, *p_wihT;
    cudaGetSymbolAddress((void**)&p_xg, g_xg);
    cudaGetSymbolAddress((void**)&p_hid, g_hid);
    cudaGetSymbolAddress((void**)&p_wihT, g_WihT);

    const int GEMM_SMEM = 6 * GSTG * 4;                       // 110592 B
    const int LSTM_SMEM = (32 * 1028 + 2 * LSTG + LSTG) * 4;  // 159232 B
    cudaFuncSetAttribute(gemm_tf32p, cudaFuncAttributeMaxDynamicSharedMemorySize, GEMM_SMEM);
    cudaFuncSetAttribute(lstm_rec2, cudaFuncAttributeMaxDynamicSharedMemorySize, LSTM_SMEM);

    transpose_k<<<dim3(G4 / 32, EMB / 32), dim3(32, 8)>>>(W_ih, EMB, G4, 0);
    transpose_k<<<dim3(G4 / 32, HID / 32), dim3(32, 8)>>>(W_hh, HID, G4, 1);
    init_k<<<(BATCH * HID + 255) / 256, 256>>>(c0);

    // Phase 1: xg = gather(emb, input) @ W_ih + b_lstm   (M=8192,N=4096,K=512)
    gemm_tf32p<<<(MTOT / 128) * (G4 / 128), 256, GEMM_SMEM>>>(
        emb, p_wihT, p_xg, b_lstm, input, MTOT, G4, EMB, EMB, 16);

    // Phase 2: 128 LSTM steps, persistent kernel, W_hh resident in SMEM
    lstm_rec2<<<128, 128, LSTM_SMEM>>>(h0);

    // Phase 3: logits = hidden @ lin_W^T + lin_b   (M=8192,N=32000,K=1024)
    // GROUPM=64 -> every m-tile concurrent, lin_W (128MB) streams DRAM once.
    gemm_tf32p<<<(MTOT / 128) * (VOCAB / 128), 256, GEMM_SMEM>>>(
        p_hid, lin_W, out, lin_b, nullptr, MTOT, VOCAB, HID, HID, 64);

    // Phase 4: append h_T, c_T after logits
    tail_k<<<(BATCH * HID + 255) / 256, 256>>>(out);
}

// round 4
// speedup vs baseline: 3.5096x; 1.7270x over previous
#include <cuda_runtime.h>
#include <cuda_fp16.h>
#include <cstdint>

#define SEQL  128
#define BATCH 64
#define EMB   512
#define HID   1024
#define VOCAB 32000
#define G4    4096      // 4*HID
#define MTOT  8192      // SEQL*BATCH

// ---------------- scratch (device globals) ----------------------------------
__device__ __align__(128) float  g_xg[(size_t)MTOT * G4];      // 134 MB fp32
__device__ __align__(128) __half g_hidh[(size_t)MTOT * HID];   // 16 MB
__device__ __align__(128) __half g_embh[(size_t)VOCAB * EMB];  // 32 MB
__device__ __align__(128) __half g_linWh[(size_t)VOCAB * HID]; // 65 MB
__device__ __align__(128) __half g_WihTh[(size_t)G4 * EMB];    // 4 MB
__device__ __align__(128) __half g_WhhTh[(size_t)G4 * HID];    // 8 MB
__device__ __align__(128) __half g_h0h[BATCH * HID];
__device__ __align__(128) float  g_c[BATCH * HID];
__device__ int g_bar[SEQL];

// ---------------- helpers ---------------------------------------------------
__device__ __forceinline__ void mma16(float* d, const uint32_t* a, const uint32_t* b) {
    asm volatile(
        "mma.sync.aligned.m16n8k16.row.col.f32.f16.f16.f32 "
        "{%0,%1,%2,%3}, {%4,%5,%6,%7}, {%8,%9}, {%0,%1,%2,%3};"
        : "+f"(d[0]), "+f"(d[1]), "+f"(d[2]), "+f"(d[3])
        : "r"(a[0]), "r"(a[1]), "r"(a[2]), "r"(a[3]), "r"(b[0]), "r"(b[1]));
}

__device__ __forceinline__ float sigmoidf_(float x) {
    return 1.0f / (1.0f + __expf(-x));
}

__device__ __forceinline__ void cp16(uint32_t dst, const void* src) {
    asm volatile("cp.async.ca.shared.global [%0], [%1], 16;" :: "r"(dst), "l"(src));
}
__device__ __forceinline__ void cp_commit() {
    asm volatile("cp.async.commit_group;");
}
template <int N>
__device__ __forceinline__ void cp_wait() {
    asm volatile("cp.async.wait_group %0;" :: "n"(N));
}

// ---------------- conversion / init / transpose / tail ----------------------
__global__ void cvt_k(const float* __restrict__ in, __half* __restrict__ out, int n4) {
    int i = blockIdx.x * blockDim.x + threadIdx.x;
    if (i < n4) {
        float4 v = *(const float4*)(in + (size_t)i * 4);
        __half2* o = (__half2*)(out + (size_t)i * 4);
        o[0] = __floats2half2_rn(v.x, v.y);
        o[1] = __floats2half2_rn(v.z, v.w);
    }
}

__global__ void init_k(const float* __restrict__ c0, const float* __restrict__ h0) {
    int i = blockIdx.x * blockDim.x + threadIdx.x;
    if (i < BATCH * HID) {
        g_c[i] = c0[i];
        g_h0h[i] = __float2half_rn(h0[i]);
    }
    if (i < SEQL) g_bar[i] = 0;
}

// in: R x C fp32 row-major -> out: C x R half row-major
__global__ void transpose_cvt_k(const float* __restrict__ in, int R, int C, int which) {
    __shared__ float tmp[32][33];
    __half* out = which ? g_WhhTh : g_WihTh;
    int cb = blockIdx.x << 5, rb = blockIdx.y << 5;
    int x = threadIdx.x, y = threadIdx.y;
#pragma unroll
    for (int i = 0; i < 32; i += 8)
        tmp[y + i][x] = in[(size_t)(rb + y + i) * C + cb + x];
    __syncthreads();
#pragma unroll
    for (int i = 0; i < 32; i += 8)
        out[(size_t)(cb + y + i) * R + rb + x] = __float2half_rn(tmp[x][y + i]);
}

__global__ void tail_k(float* __restrict__ out) {
    int i = blockIdx.x * blockDim.x + threadIdx.x;
    if (i < BATCH * HID) {
        const size_t LOG = (size_t)MTOT * VOCAB;
        out[LOG + i] = __half2float(g_hidh[(size_t)(SEQL - 1) * BATCH * HID + i]);
        out[LOG + (size_t)BATCH * HID + i] = g_c[i];
    }
}

// ---------------- pipelined fp16 GEMM:  C = A(MxK) @ B^T(NxK) + bias --------
// A row-major half (optional row gather); B is N x K row-major half.
// BM=BN=128, BK=32, 256 threads, 3-stage cp.async pipeline.
// smem: 3 stages x (A 128x40 + B 128x40) halves = 61440 B dynamic.
#define HSTG 5120   // halves per stage per matrix = 128*40
__global__ __launch_bounds__(256, 2)
void gemm_h(const __half* __restrict__ A, const __half* __restrict__ B,
            float* __restrict__ C, const float* __restrict__ bias,
            const int* __restrict__ gidx,
            int M, int N, int K, int lda, int GROUPM)
{
    extern __shared__ __half hsm[];
    __half* Asm = hsm;               // [3][128][40]
    __half* Bsm = hsm + 3 * HSTG;    // [3][128][40]
    __shared__ int sidx[128];

    const int grid_m = M >> 7, grid_n = N >> 7;
    const int pid = blockIdx.x;
    const int width = GROUPM * grid_n;
    const int grp = pid / width;
    const int first = grp * GROUPM;
    const int gsz = min(grid_m - first, GROUPM);
    const int pm = first + (pid % width) % gsz;
    const int pn = (pid % width) / gsz;
    const int m0 = pm << 7, n0 = pn << 7;

    const int tid = threadIdx.x, lane = tid & 31, wid = tid >> 5;
    const int wm = (wid & 1) << 6;
    const int wn = (wid >> 1) << 5;

    if (tid < 128) sidx[tid] = gidx ? gidx[m0 + tid] : (m0 + tid);
    __syncthreads();

    const uint32_t asb = (uint32_t)__cvta_generic_to_shared(Asm);
    const uint32_t bsb = (uint32_t)__cvta_generic_to_shared(Bsm);

    const int NK = K >> 5;

    auto load_stage = [&](int st, int kt) {
#pragma unroll
        for (int i = 0; i < 2; i++) {
            int l = tid + (i << 8);           // 0..511
            int r = l >> 2, kq = (l & 3) << 3; // 8-half chunks
            cp16(asb + (uint32_t)(st * HSTG + r * 40 + kq) * 2,
                 A + (size_t)sidx[r] * lda + kt + kq);
            cp16(bsb + (uint32_t)(st * HSTG + r * 40 + kq) * 2,
                 B + (size_t)(n0 + r) * K + kt + kq);
        }
    };

    float acc[4][4][4];
#pragma unroll
    for (int i = 0; i < 4; i++)
#pragma unroll
        for (int j = 0; j < 4; j++)
#pragma unroll
            for (int q = 0; q < 4; q++) acc[i][j][q] = 0.f;

    load_stage(0, 0); cp_commit();
    load_stage(1, 32); cp_commit();

    const int c2 = (lane & 3) << 1;
    for (int it = 0; it < NK; it++) {
        if (it + 2 < NK) load_stage((it + 2) % 3, (it + 2) << 5);
        cp_commit();
        cp_wait<2>();
        __syncthreads();

        const __half* Ab = Asm + (it % 3) * HSTG;
        const __half* Bb = Bsm + (it % 3) * HSTG;
#pragma unroll
        for (int ks = 0; ks < 2; ks++) {
            const int k0 = ks << 4;
            uint32_t af[4][4], bf[4][2];
#pragma unroll
            for (int fm = 0; fm < 4; fm++) {
                int r = wm + (fm << 4) + (lane >> 2);
                af[fm][0] = *(const uint32_t*)(Ab + r * 40 + k0 + c2);
                af[fm][1] = *(const uint32_t*)(Ab + (r + 8) * 40 + k0 + c2);
                af[fm][2] = *(const uint32_t*)(Ab + r * 40 + k0 + c2 + 8);
                af[fm][3] = *(const uint32_t*)(Ab + (r + 8) * 40 + k0 + c2 + 8);
            }
#pragma unroll
            for (int fn = 0; fn < 4; fn++) {
                int c = wn + (fn << 3) + (lane >> 2);
                bf[fn][0] = *(const uint32_t*)(Bb + c * 40 + k0 + c2);
                bf[fn][1] = *(const uint32_t*)(Bb + c * 40 + k0 + c2 + 8);
            }
#pragma unroll
            for (int fm = 0; fm < 4; fm++)
#pragma unroll
                for (int fn = 0; fn < 4; fn++)
                    mma16(acc[fm][fn], af[fm], bf[fn]);
        }
        __syncthreads();
    }

#pragma unroll
    for (int fm = 0; fm < 4; fm++) {
        int r = m0 + wm + (fm << 4) + (lane >> 2);
#pragma unroll
        for (int fn = 0; fn < 4; fn++) {
            int c = n0 + wn + (fn << 3) + c2;
            float b0 = bias[c], b1 = bias[c + 1];
            float2 v0 = make_float2(acc[fm][fn][0] + b0, acc[fm][fn][1] + b1);
            float2 v1 = make_float2(acc[fm][fn][2] + b0, acc[fm][fn][3] + b1);
            *(float2*)(C + (size_t)r * N + c) = v0;
            *(float2*)(C + (size_t)(r + 8) * N + c) = v1;
        }
    }
}

// ---------------- persistent LSTM recurrence (fp16 MMA) ----------------------
// 128 blocks x 128 threads. Block b owns 8 hidden units; its 32 gate-rows of
// W_hh live in SMEM (half) for all 128 steps. h tile double-buffered in K=256
// chunks (8 syncs/step). Software global barrier between steps.
#define LROW 264     // padded halves per A row chunk (256+8)
#define LAST 16896   // halves per A stage = 64*264
__global__ __launch_bounds__(128, 1)
void lstm_h(void)
{
    extern __shared__ __half dsm[];
    __half* Bw  = dsm;                       // [32][1032] halves
    __half* Asm = dsm + 32 * 1032;           // [2][64][264] halves
    float*  Gs  = (float*)(Asm + 2 * LAST);  // [64][36]

    const int tid = threadIdx.x, lane = tid & 31, wid = tid >> 5;
    const int u0 = blockIdx.x << 3;          // 8 units per block

    // Load this block's W_hh slice once (half, padded rows).
    for (int idx = tid; idx < 32 * 128; idx += 128) {
        int r = idx >> 7, off = (idx & 127) << 3;
        int grow = ((r >> 3) << 10) + u0 + (r & 7);   // gate*HID + unit
        *(uint4*)(Bw + r * 1032 + off) =
            *(const uint4*)(g_WhhTh + (size_t)grow * HID + off);
    }
    __syncthreads();

    const uint32_t asb = (uint32_t)__cvta_generic_to_shared(Asm);
    const int c2 = (lane & 3) << 1;

    for (int t = 0; t < SEQL; t++) {
        const __half* hp = t ? (g_hidh + (size_t)(t - 1) * BATCH * HID) : g_h0h;

        float acc[4][4];
#pragma unroll
        for (int i = 0; i < 4; i++)
#pragma unroll
            for (int q = 0; q < 4; q++) acc[i][q] = 0.f;

        auto loadA = [&](int st, int kc) {
#pragma unroll
            for (int i = 0; i < 16; i++) {
                int l = tid + (i << 7);            // 0..2047
                int r = l >> 5, q = (l & 31) << 3; // 64 rows x 32 8-half chunks
                cp16(asb + (uint32_t)(st * LAST + r * LROW + q) * 2,
                     hp + (size_t)r * HID + kc + q);
            }
        };

        loadA(0, 0); cp_commit();
        for (int ch = 0; ch < 4; ch++) {
            if (ch < 3) { loadA((ch + 1) & 1, (ch + 1) << 8); cp_commit(); cp_wait<1>(); }
            else         cp_wait<0>();
            __syncthreads();

            const __half* Ab = Asm + (ch & 1) * LAST;
            const int kb = ch << 8;
#pragma unroll
            for (int ksl = 0; ksl < 16; ksl++) {
                const int k0 = ksl << 4;
                uint32_t af[4][4], bf[2];
#pragma unroll
                for (int fm = 0; fm < 4; fm++) {
                    int r = (fm << 4) + (lane >> 2);
                    af[fm][0] = *(const uint32_t*)(Ab + r * LROW + k0 + c2);
                    af[fm][1] = *(const uint32_t*)(Ab + (r + 8) * LROW + k0 + c2);
                    af[fm][2] = *(const uint32_t*)(Ab + r * LROW + k0 + c2 + 8);
                    af[fm][3] = *(const uint32_t*)(Ab + (r + 8) * LROW + k0 + c2 + 8);
                }
                int c = (wid << 3) + (lane >> 2);
                bf[0] = *(const uint32_t*)(Bw + c * 1032 + kb + k0 + c2);
                bf[1] = *(const uint32_t*)(Bw + c * 1032 + kb + k0 + c2 + 8);
#pragma unroll
                for (int fm = 0; fm < 4; fm++) mma16(acc[fm], af[fm], bf);
            }
            __syncthreads();
        }

        // spill gate tile (64 batch x 32 gate-cols) to smem
#pragma unroll
        for (int fm = 0; fm < 4; fm++) {
            int r = (fm << 4) + (lane >> 2);
            int c = (wid << 3) + c2;
            Gs[r * 36 + c]           = acc[fm][0];
            Gs[r * 36 + c + 1]       = acc[fm][1];
            Gs[(r + 8) * 36 + c]     = acc[fm][2];
            Gs[(r + 8) * 36 + c + 1] = acc[fm][3];
        }
        __syncthreads();

        // pointwise: 64 batch x 8 units = 512 elems / 128 threads
#pragma unroll
        for (int i = 0; i < 4; i++) {
            int p = tid + (i << 7);
            int row = p >> 3, u = p & 7;
            size_t xb = ((size_t)(t * BATCH + row)) * G4 + u0 + u;
            float gi = Gs[row * 36 + u]      + g_xg[xb];
            float gf = Gs[row * 36 + 8 + u]  + g_xg[xb + HID];
            float gg = Gs[row * 36 + 16 + u] + g_xg[xb + 2 * HID];
            float go = Gs[row * 36 + 24 + u] + g_xg[xb + 3 * HID];
            float iv = sigmoidf_(gi);
            float fv = sigmoidf_(gf);
            float gv = tanhf(gg);
            float ov = sigmoidf_(go);
            int ci = row * HID + u0 + u;
            float cv = fv * g_c[ci] + iv * gv;
            g_c[ci] = cv;
            g_hidh[(size_t)(t * BATCH + row) * HID + u0 + u] =
                __float2half_rn(ov * tanhf(cv));
        }

        // global barrier: all 128 blocks finish step t before step t+1
        __threadfence();
        __syncthreads();
        if (tid == 0) {
            atomicAdd(&g_bar[t], 1);
            while (*(volatile int*)&g_bar[t] < 128) __nanosleep(32);
        }
        __syncthreads();
    }
}

// ---------------- launch -----------------------------------------------------
extern "C" void kernel_launch(void* const* d_in, const int* in_sizes, int n_in,
                              void* d_out, int out_size)
{
    const int*   input  = (const int*)d_in[0];
    const float* emb    = (const float*)d_in[1];
    const float* W_ih   = (const float*)d_in[2];
    const float* W_hh   = (const float*)d_in[3];
    const float* b_lstm = (const float*)d_in[4];
    const float* lin_W  = (const float*)d_in[5];
    const float* lin_b  = (const float*)d_in[6];
    const float* h0     = (const float*)d_in[7];
    const float* c0     = (const float*)d_in[8];
    float* out = (float*)d_out;

    float  *p_xg;
    __half *p_embh, *p_linWh, *p_wihTh, *p_hidh;
    cudaGetSymbolAddress((void**)&p_xg, g_xg);
    cudaGetSymbolAddress((void**)&p_embh, g_embh);
    cudaGetSymbolAddress((void**)&p_linWh, g_linWh);
    cudaGetSymbolAddress((void**)&p_wihTh, g_WihTh);
    cudaGetSymbolAddress((void**)&p_hidh, g_hidh);

    const int GEMM_SMEM = 6 * HSTG * 2;                                // 61440 B
    const int LSTM_SMEM = (32 * 1032 + 2 * LAST) * 2 + 64 * 36 * 4;    // 142848 B
    cudaFuncSetAttribute(gemm_h, cudaFuncAttributeMaxDynamicSharedMemorySize, GEMM_SMEM);
    cudaFuncSetAttribute(lstm_h, cudaFuncAttributeMaxDynamicSharedMemorySize, LSTM_SMEM);

    // conversions + transposes + init
    cvt_k<<<(VOCAB * EMB / 4 + 255) / 256, 256>>>(emb, p_embh, VOCAB * EMB / 4);
    cvt_k<<<(VOCAB * HID / 4 + 255) / 256, 256>>>(lin_W, p_linWh, VOCAB * HID / 4);
    transpose_cvt_k<<<dim3(G4 / 32, EMB / 32), dim3(32, 8)>>>(W_ih, EMB, G4, 0);
    transpose_cvt_k<<<dim3(G4 / 32, HID / 32), dim3(32, 8)>>>(W_hh, HID, G4, 1);
    init_k<<<(BATCH * HID + 255) / 256, 256>>>(c0, h0);

    // Phase 1: xg = gather(emb, input) @ W_ih + b_lstm   (M=8192,N=4096,K=512)
    gemm_h<<<(MTOT / 128) * (G4 / 128), 256, GEMM_SMEM>>>(
        p_embh, p_wihTh, p_xg, b_lstm, input, MTOT, G4, EMB, EMB, 16);

    // Phase 2: 128 LSTM steps, persistent kernel, W_hh resident in SMEM
    lstm_h<<<128, 128, LSTM_SMEM>>>();

    // Phase 3: logits = hidden @ lin_W^T + lin_b   (M=8192,N=32000,K=1024)
    gemm_h<<<(MTOT / 128) * (VOCAB / 128), 256, GEMM_SMEM>>>(
        p_hidh, p_linWh, out, lin_b, nullptr, MTOT, VOCAB, HID, HID, 64);

    // Phase 4: append h_T, c_T after logits
    tail_k<<<(BATCH * HID + 255) / 256, 256>>>(out);
}

// round 6
// speedup vs baseline: 3.9223x; 1.1176x over previous
#include <cuda_runtime.h>
#include <cuda_fp16.h>
#include <cstdint>

#define SEQL  128
#define BATCH 64
#define EMB   512
#define HID   1024
#define VOCAB 32000
#define G4    4096      // 4*HID
#define MTOT  8192      // SEQL*BATCH

// ---------------- scratch (device globals) ----------------------------------
__device__ __align__(128) float  g_xg[(size_t)MTOT * G4];      // 134 MB fp32
__device__ __align__(128) __half g_hidh[(size_t)MTOT * HID];   // 16 MB
__device__ __align__(128) __half g_embh[(size_t)VOCAB * EMB];  // 32 MB
__device__ __align__(128) __half g_linWh[(size_t)VOCAB * HID]; // 65 MB
__device__ __align__(128) __half g_WihTh[(size_t)G4 * EMB];    // 4 MB
__device__ __align__(128) __half g_WhhTh[(size_t)G4 * HID];    // 8 MB
__device__ __align__(128) __half g_h0h[BATCH * HID];
__device__ __align__(128) float  g_c[BATCH * HID];
__device__ int g_bar[SEQL];

// ---------------- helpers ---------------------------------------------------
__device__ __forceinline__ void mma16(float* d, const uint32_t* a, const uint32_t* b) {
    asm volatile(
        "mma.sync.aligned.m16n8k16.row.col.f32.f16.f16.f32 "
        "{%0,%1,%2,%3}, {%4,%5,%6,%7}, {%8,%9}, {%0,%1,%2,%3};"
        : "+f"(d[0]), "+f"(d[1]), "+f"(d[2]), "+f"(d[3])
        : "r"(a[0]), "r"(a[1]), "r"(a[2]), "r"(a[3]), "r"(b[0]), "r"(b[1]));
}

__device__ __forceinline__ void ldm_x4(uint32_t* d, uint32_t addr) {
    asm volatile("ldmatrix.sync.aligned.m8n8.x4.shared.b16 {%0,%1,%2,%3}, [%4];"
        : "=r"(d[0]), "=r"(d[1]), "=r"(d[2]), "=r"(d[3]) : "r"(addr));
}
__device__ __forceinline__ void ldm_x2(uint32_t* d, uint32_t addr) {
    asm volatile("ldmatrix.sync.aligned.m8n8.x2.shared.b16 {%0,%1}, [%2];"
        : "=r"(d[0]), "=r"(d[1]) : "r"(addr));
}

__device__ __forceinline__ float sigmoidf_(float x) {
    return 1.0f / (1.0f + __expf(-x));
}

__device__ __forceinline__ void cp16(uint32_t dst, const void* src) {
    asm volatile("cp.async.cg.shared.global [%0], [%1], 16;" :: "r"(dst), "l"(src));
}
__device__ __forceinline__ void cp_commit() {
    asm volatile("cp.async.commit_group;");
}
template <int N>
__device__ __forceinline__ void cp_wait() {
    asm volatile("cp.async.wait_group %0;" :: "n"(N));
}

// XOR-swizzled smem byte offset for row r, half-offset ho within the row.
// Swizzles the 16B-chunk index within each 128B group by (r & 7):
// conflict-free for ldmatrix (rows stride = rowbytes multiple of 128B wraps banks).
__device__ __forceinline__ uint32_t swz(uint32_t r, uint32_t ho, uint32_t rowbytes) {
    uint32_t b = ho << 1;
    uint32_t grp = b & ~127u;
    uint32_t ci = (b >> 4) & 7u;
    return r * rowbytes + grp + (((ci ^ (r & 7u)) << 4) | (b & 15u));
}

// ---------------- conversion / init / transpose / tail ----------------------
__global__ void cvt_k(const float* __restrict__ in, __half* __restrict__ out, int n4) {
    int i = blockIdx.x * blockDim.x + threadIdx.x;
    if (i < n4) {
        float4 v = *(const float4*)(in + (size_t)i * 4);
        __half2* o = (__half2*)(out + (size_t)i * 4);
        o[0] = __floats2half2_rn(v.x, v.y);
        o[1] = __floats2half2_rn(v.z, v.w);
    }
}

__global__ void init_k(const float* __restrict__ c0, const float* __restrict__ h0) {
    int i = blockIdx.x * blockDim.x + threadIdx.x;
    if (i < BATCH * HID) {
        g_c[i] = c0[i];
        g_h0h[i] = __float2half_rn(h0[i]);
    }
    if (i < SEQL) g_bar[i] = 0;
}

// in: R x C fp32 row-major -> out: C x R half row-major
__global__ void transpose_cvt_k(const float* __restrict__ in, int R, int C, int which) {
    __shared__ float tmp[32][33];
    __half* out = which ? g_WhhTh : g_WihTh;
    int cb = blockIdx.x << 5, rb = blockIdx.y << 5;
    int x = threadIdx.x, y = threadIdx.y;
#pragma unroll
    for (int i = 0; i < 32; i += 8)
        tmp[y + i][x] = in[(size_t)(rb + y + i) * C + cb + x];
    __syncthreads();
#pragma unroll
    for (int i = 0; i < 32; i += 8)
        out[(size_t)(cb + y + i) * R + rb + x] = __float2half_rn(tmp[x][y + i]);
}

__global__ void tail_k(float* __restrict__ out) {
    int i = blockIdx.x * blockDim.x + threadIdx.x;
    if (i < BATCH * HID) {
        const size_t LOG = (size_t)MTOT * VOCAB;
        out[LOG + i] = __half2float(g_hidh[(size_t)(SEQL - 1) * BATCH * HID + i]);
        out[LOG + (size_t)BATCH * HID + i] = g_c[i];
    }
}

// ---------------- pipelined fp16 GEMM:  C = A(MxK) @ B^T(NxK) + bias --------
// BM=BN=128, BK=64 (one SW128 row per chunk), 256 threads, 3-stage cp.async,
// ldmatrix fragment loads from XOR-swizzled smem (conflict-free, no padding).
#define ASTG_B 16384              // A bytes per stage (128 rows x 128B)
#define STGB   (2 * ASTG_B)       // stage bytes (A + B)
#define GEMM_SMEM (3 * STGB)      // 98304 B
__global__ __launch_bounds__(256, 2)
void gemm_h(const __half* __restrict__ A, const __half* __restrict__ B,
            float* __restrict__ C, const float* __restrict__ bias,
            const int* __restrict__ gidx,
            int M, int N, int K, int lda, int GROUPM)
{
    extern __shared__ char smem[];
    const uint32_t sb = (uint32_t)__cvta_generic_to_shared(smem);
    __shared__ int sidx[128];

    const int grid_m = M >> 7, grid_n = N >> 7;
    const int pid = blockIdx.x;
    const int width = GROUPM * grid_n;
    const int grp = pid / width;
    const int first = grp * GROUPM;
    const int gsz = min(grid_m - first, GROUPM);
    const int pm = first + (pid % width) % gsz;
    const int pn = (pid % width) / gsz;
    const int m0 = pm << 7, n0 = pn << 7;

    const int tid = threadIdx.x, lane = tid & 31, wid = tid >> 5;
    const int wm = (wid & 1) << 6;
    const int wn = (wid >> 1) << 5;

    if (tid < 128) sidx[tid] = gidx ? gidx[m0 + tid] : (m0 + tid);
    __syncthreads();

    const int NCH = K >> 6;

    auto load_stage = [&](int st, int kt) {
        uint32_t stb = sb + (uint32_t)st * STGB;
#pragma unroll
        for (int i = 0; i < 4; i++) {
            int l = tid + (i << 8);       // 0..1023
            int r = l >> 3, c8 = (l & 7) << 3;
            cp16(stb + swz(r, c8, 128), A + (size_t)sidx[r] * lda + kt + c8);
            cp16(stb + ASTG_B + swz(r, c8, 128), B + (size_t)(n0 + r) * K + kt + c8);
        }
    };

    float acc[4][4][4];
#pragma unroll
    for (int i = 0; i < 4; i++)
#pragma unroll
        for (int j = 0; j < 4; j++)
#pragma unroll
            for (int q = 0; q < 4; q++) acc[i][j][q] = 0.f;

    load_stage(0, 0); cp_commit();
    if (NCH > 1) load_stage(1, 64);
    cp_commit();

    const int mm = lane >> 3, r8 = lane & 7;
    for (int it = 0; it < NCH; it++) {
        if (it + 2 < NCH) load_stage((it + 2) % 3, (it + 2) << 6);
        cp_commit();
        cp_wait<2>();
        __syncthreads();

        uint32_t Ab = sb + (uint32_t)(it % 3) * STGB;
        uint32_t Bb = Ab + ASTG_B;
#pragma unroll
        for (int ks = 0; ks < 4; ks++) {
            uint32_t af[4][4], bf[4][2];
#pragma unroll
            for (int fm = 0; fm < 4; fm++) {
                int row = wm + (fm << 4) + r8 + ((mm & 1) << 3);
                int ko = (ks << 4) + ((mm >> 1) << 3);
                ldm_x4(af[fm], Ab + swz(row, ko, 128));
            }
#pragma unroll
            for (int h = 0; h < 2; h++) {
                uint32_t t4[4];
                int col = wn + (h << 4) + ((mm >> 1) << 3) + r8;
                int ko = (ks << 4) + ((mm & 1) << 3);
                ldm_x4(t4, Bb + swz(col, ko, 128));
                bf[h * 2][0] = t4[0]; bf[h * 2][1] = t4[1];
                bf[h * 2 + 1][0] = t4[2]; bf[h * 2 + 1][1] = t4[3];
            }
#pragma unroll
            for (int fm = 0; fm < 4; fm++)
#pragma unroll
                for (int fn = 0; fn < 4; fn++)
                    mma16(acc[fm][fn], af[fm], bf[fn]);
        }
        __syncthreads();
    }

    const int c2 = (lane & 3) << 1;
#pragma unroll
    for (int fm = 0; fm < 4; fm++) {
        int r = m0 + wm + (fm << 4) + (lane >> 2);
#pragma unroll
        for (int fn = 0; fn < 4; fn++) {
            int c = n0 + wn + (fn << 3) + c2;
            float b0 = bias[c], b1 = bias[c + 1];
            float2 v0 = make_float2(acc[fm][fn][0] + b0, acc[fm][fn][1] + b1);
            float2 v1 = make_float2(acc[fm][fn][2] + b0, acc[fm][fn][3] + b1);
            *(float2*)(C + (size_t)r * N + c) = v0;
            *(float2*)(C + (size_t)(r + 8) * N + c) = v1;
        }
    }
}

// ---------------- persistent LSTM recurrence (fp16 MMA, ldmatrix) ------------
// 64 blocks x 256 threads. Block b owns 16 hidden units -> 64 gate-rows of
// W_hh resident in SMEM (swizzled half, 128 KB) for all 128 steps. h tile
// double-buffered in K=256 chunks. Warp w owns gate-cols [8w, 8w+8).
#define LW_B   (64 * 2048)        // W slice bytes: 64 rows x 1024 halves
#define LA_B   (64 * 512)         // A stage bytes: 64 rows x 256 halves
#define LSTM_SMEM (LW_B + 2 * LA_B + 64 * 68 * 4)   // 214016 B
__global__ __launch_bounds__(256, 1)
void lstm_h(void)
{
    extern __shared__ char smem[];
    const uint32_t sb = (uint32_t)__cvta_generic_to_shared(smem);
    const uint32_t bwb = sb;
    const uint32_t ab = sb + LW_B;
    float* Gs = (float*)(smem + LW_B + 2 * LA_B);   // [64][68]

    const int tid = threadIdx.x, lane = tid & 31, wid = tid >> 5;
    const int u0 = blockIdx.x << 4;   // 16 units per block
    const int wc = wid << 3;          // warp's 8 gate-cols

    // Resident W_hh slice: row c (gate-col) = gate(c>>4)*HID + u0 + (c&15)
    for (int idx = tid; idx < 64 * 128; idx += 256) {
        int r = idx >> 7, c8 = (idx & 127) << 3;
        int grow = ((r >> 4) << 10) + u0 + (r & 15);
        cp16(bwb + swz(r, c8, 2048), g_WhhTh + (size_t)grow * HID + c8);
    }
    cp_commit(); cp_wait<0>();
    __syncthreads();

    const int mm = lane >> 3, r8 = lane & 7;
    const int sel = mm & 1;

    for (int t = 0; t < SEQL; t++) {
        const __half* hp = t ? (g_hidh + (size_t)(t - 1) * BATCH * HID) : g_h0h;

        float acc[4][4];
#pragma unroll
        for (int i = 0; i < 4; i++)
#pragma unroll
            for (int q = 0; q < 4; q++) acc[i][q] = 0.f;

        auto loadA = [&](int st, int kc) {
#pragma unroll
            for (int i = 0; i < 8; i++) {
                int l = tid + (i << 8);        // 0..2047
                int r = l >> 5, c8 = (l & 31) << 3;
                cp16(ab + (uint32_t)st * LA_B + swz(r, c8, 512),
                     hp + (size_t)r * HID + kc + c8);
            }
        };

        loadA(0, 0); cp_commit();
        for (int ch = 0; ch < 4; ch++) {
            if (ch < 3) { loadA((ch + 1) & 1, (ch + 1) << 8); cp_commit(); cp_wait<1>(); }
            else         cp_wait<0>();
            __syncthreads();

            uint32_t Ab = ab + (uint32_t)(ch & 1) * LA_B;
            const int kb = ch << 8;
#pragma unroll
            for (int ks = 0; ks < 16; ks++) {
                uint32_t af[4][4], bf[2];
#pragma unroll
                for (int fm = 0; fm < 4; fm++) {
                    int row = (fm << 4) + r8 + ((mm & 1) << 3);
                    int ko = (ks << 4) + ((mm >> 1) << 3);
                    ldm_x4(af[fm], Ab + swz(row, ko, 512));
                }
                ldm_x2(bf, bwb + swz(wc + r8, kb + (ks << 4) + (sel << 3), 2048));
#pragma unroll
                for (int fm = 0; fm < 4; fm++) mma16(acc[fm], af[fm], bf);
            }
            __syncthreads();
        }

        // spill gate tile (64 batch x 64 gate-cols) to smem
        const int c2 = (lane & 3) << 1;
#pragma unroll
        for (int fm = 0; fm < 4; fm++) {
            int r = (fm << 4) + (lane >> 2);
            int c = wc + c2;
            Gs[r * 68 + c]           = acc[fm][0];
            Gs[r * 68 + c + 1]       = acc[fm][1];
            Gs[(r + 8) * 68 + c]     = acc[fm][2];
            Gs[(r + 8) * 68 + c + 1] = acc[fm][3];
        }
        __syncthreads();

        // pointwise: 64 batch x 16 units = 1024 elems / 256 threads
#pragma unroll
        for (int i = 0; i < 4; i++) {
            int p = tid + (i << 8);
            int row = p >> 4, u = p & 15;
            size_t xb = ((size_t)(t * BATCH + row)) * G4 + u0 + u;
            float gi = Gs[row * 68 + u]      + g_xg[xb];
            float gf = Gs[row * 68 + 16 + u] + g_xg[xb + HID];
            float gg = Gs[row * 68 + 32 + u] + g_xg[xb + 2 * HID];
            float go = Gs[row * 68 + 48 + u] + g_xg[xb + 3 * HID];
            float iv = sigmoidf_(gi);
            float fv = sigmoidf_(gf);
            float gv = tanhf(gg);
            float ov = sigmoidf_(go);
            int ci = row * HID + u0 + u;
            float cv = fv * g_c[ci] + iv * gv;
            g_c[ci] = cv;
            g_hidh[(size_t)(t * BATCH + row) * HID + u0 + u] =
                __float2half_rn(ov * tanhf(cv));
        }

        // global barrier: all 64 blocks finish step t before step t+1
        __threadfence();
        __syncthreads();
        if (tid == 0) {
            atomicAdd(&g_bar[t], 1);
            while (*(volatile int*)&g_bar[t] < 64) __nanosleep(32);
        }
        __syncthreads();
    }
}

// ---------------- launch -----------------------------------------------------
extern "C" void kernel_launch(void* const* d_in, const int* in_sizes, int n_in,
                              void* d_out, int out_size)
{
    const int*   input  = (const int*)d_in[0];
    const float* emb    = (const float*)d_in[1];
    const float* W_ih   = (const float*)d_in[2];
    const float* W_hh   = (const float*)d_in[3];
    const float* b_lstm = (const float*)d_in[4];
    const float* lin_W  = (const float*)d_in[5];
    const float* lin_b  = (const float*)d_in[6];
    const float* h0     = (const float*)d_in[7];
    const float* c0     = (const float*)d_in[8];
    float* out = (float*)d_out;

    float  *p_xg;
    __half *p_embh, *p_linWh, *p_wihTh, *p_hidh;
    cudaGetSymbolAddress((void**)&p_xg, g_xg);
    cudaGetSymbolAddress((void**)&p_embh, g_embh);
    cudaGetSymbolAddress((void**)&p_linWh, g_linWh);
    cudaGetSymbolAddress((void**)&p_wihTh, g_WihTh);
    cudaGetSymbolAddress((void**)&p_hidh, g_hidh);

    cudaFuncSetAttribute(gemm_h, cudaFuncAttributeMaxDynamicSharedMemorySize, GEMM_SMEM);
    cudaFuncSetAttribute(lstm_h, cudaFuncAttributeMaxDynamicSharedMemorySize, LSTM_SMEM);

    cvt_k<<<(VOCAB * EMB / 4 + 255) / 256, 256>>>(emb, p_embh, VOCAB * EMB / 4);
    cvt_k<<<(VOCAB * HID / 4 + 255) / 256, 256>>>(lin_W, p_linWh, VOCAB * HID / 4);
    transpose_cvt_k<<<dim3(G4 / 32, EMB / 32), dim3(32, 8)>>>(W_ih, EMB, G4, 0);
    transpose_cvt_k<<<dim3(G4 / 32, HID / 32), dim3(32, 8)>>>(W_hh, HID, G4, 1);
    init_k<<<(BATCH * HID + 255) / 256, 256>>>(c0, h0);

    // Phase 1: xg = gather(emb, input) @ W_ih + b_lstm   (M=8192,N=4096,K=512)
    gemm_h<<<(MTOT / 128) * (G4 / 128), 256, GEMM_SMEM>>>(
        p_embh, p_wihTh, p_xg, b_lstm, input, MTOT, G4, EMB, EMB, 16);

    // Phase 2: 128 LSTM steps, persistent kernel, W_hh resident in SMEM
    lstm_h<<<64, 256, LSTM_SMEM>>>();

    // Phase 3: logits = hidden @ lin_W^T + lin_b   (M=8192,N=32000,K=1024)
    gemm_h<<<(MTOT / 128) * (VOCAB / 128), 256, GEMM_SMEM>>>(
        p_hidh, p_linWh, out, lin_b, nullptr, MTOT, VOCAB, HID, HID, 64);

    // Phase 4: append h_T, c_T after logits
    tail_k<<<(BATCH * HID + 255) / 256, 256>>>(out);
}

// round 7
// speedup vs baseline: 4.6805x; 1.1933x over previous
#include <cuda_runtime.h>
#include <cuda_fp16.h>
#include <cstdint>

#define SEQL  128
#define BATCH 64
#define EMB   512
#define HID   1024
#define VOCAB 32000
#define G4    4096      // 4*HID
#define MTOT  8192      // SEQL*BATCH
#define NT_N  125       // 32000 / 256
#define NTILE (64 * NT_N)

// ---------------- scratch (device globals) ----------------------------------
__device__ __align__(128) float  g_xg[(size_t)MTOT * G4];      // 134 MB fp32
__device__ __align__(128) __half g_hidh[(size_t)MTOT * HID];   // 16 MB
__device__ __align__(128) __half g_embh[(size_t)VOCAB * EMB];  // 32 MB
__device__ __align__(128) __half g_linWh[(size_t)VOCAB * HID]; // 65 MB
__device__ __align__(128) __half g_WihTh[(size_t)G4 * EMB];    // 4 MB
__device__ __align__(128) __half g_WhhTh[(size_t)G4 * HID];    // 8 MB
__device__ __align__(128) __half g_h0h[BATCH * HID];
__device__ __align__(128) float  g_c[BATCH * HID];
__device__ int g_bar[SEQL];
__device__ int g_prog;
__device__ int g_tile;

// ---------------- helpers ---------------------------------------------------
__device__ __forceinline__ void mma16(float* d, const uint32_t* a, const uint32_t* b) {
    asm volatile(
        "mma.sync.aligned.m16n8k16.row.col.f32.f16.f16.f32 "
        "{%0,%1,%2,%3}, {%4,%5,%6,%7}, {%8,%9}, {%0,%1,%2,%3};"
        : "+f"(d[0]), "+f"(d[1]), "+f"(d[2]), "+f"(d[3])
        : "r"(a[0]), "r"(a[1]), "r"(a[2]), "r"(a[3]), "r"(b[0]), "r"(b[1]));
}

__device__ __forceinline__ void ldm_x4(uint32_t* d, uint32_t addr) {
    asm volatile("ldmatrix.sync.aligned.m8n8.x4.shared.b16 {%0,%1,%2,%3}, [%4];"
        : "=r"(d[0]), "=r"(d[1]), "=r"(d[2]), "=r"(d[3]) : "r"(addr));
}
__device__ __forceinline__ void ldm_x2(uint32_t* d, uint32_t addr) {
    asm volatile("ldmatrix.sync.aligned.m8n8.x2.shared.b16 {%0,%1}, [%2];"
        : "=r"(d[0]), "=r"(d[1]) : "r"(addr));
}

__device__ __forceinline__ float sigmoidf_(float x) {
    return 1.0f / (1.0f + __expf(-x));
}

__device__ __forceinline__ void cp16(uint32_t dst, const void* src) {
    asm volatile("cp.async.cg.shared.global [%0], [%1], 16;" :: "r"(dst), "l"(src));
}
__device__ __forceinline__ void cp_commit() {
    asm volatile("cp.async.commit_group;");
}
template <int N>
__device__ __forceinline__ void cp_wait() {
    asm volatile("cp.async.wait_group %0;" :: "n"(N));
}

// XOR-swizzled smem byte offset for row r, half-offset ho within the row.
__device__ __forceinline__ uint32_t swz(uint32_t r, uint32_t ho, uint32_t rowbytes) {
    uint32_t b = ho << 1;
    uint32_t grp = b & ~127u;
    uint32_t ci = (b >> 4) & 7u;
    return r * rowbytes + grp + (((ci ^ (r & 7u)) << 4) | (b & 15u));
}

// ---------------- conversion / init / transpose / tail ----------------------
__global__ void cvt_k(const float* __restrict__ in, __half* __restrict__ out, int n4) {
    int i = blockIdx.x * blockDim.x + threadIdx.x;
    if (i < n4) {
        float4 v = *(const float4*)(in + (size_t)i * 4);
        __half2* o = (__half2*)(out + (size_t)i * 4);
        o[0] = __floats2half2_rn(v.x, v.y);
        o[1] = __floats2half2_rn(v.z, v.w);
    }
}

__global__ void init_k(const float* __restrict__ c0, const float* __restrict__ h0) {
    int i = blockIdx.x * blockDim.x + threadIdx.x;
    if (i < BATCH * HID) {
        g_c[i] = c0[i];
        g_h0h[i] = __float2half_rn(h0[i]);
    }
    if (i < SEQL) g_bar[i] = 0;
    if (i == 0) { g_prog = 0; g_tile = 0; }
}

// in: R x C fp32 row-major -> out: C x R half row-major
__global__ void transpose_cvt_k(const float* __restrict__ in, int R, int C, int which) {
    __shared__ float tmp[32][33];
    __half* out = which ? g_WhhTh : g_WihTh;
    int cb = blockIdx.x << 5, rb = blockIdx.y << 5;
    int x = threadIdx.x, y = threadIdx.y;
#pragma unroll
    for (int i = 0; i < 32; i += 8)
        tmp[y + i][x] = in[(size_t)(rb + y + i) * C + cb + x];
    __syncthreads();
#pragma unroll
    for (int i = 0; i < 32; i += 8)
        out[(size_t)(cb + y + i) * R + rb + x] = __float2half_rn(tmp[x][y + i]);
}

__global__ void tail_k(float* __restrict__ out) {
    int i = blockIdx.x * blockDim.x + threadIdx.x;
    if (i < BATCH * HID) {
        const size_t LOG = (size_t)MTOT * VOCAB;
        out[LOG + i] = __half2float(g_hidh[(size_t)(SEQL - 1) * BATCH * HID + i]);
        out[LOG + (size_t)BATCH * HID + i] = g_c[i];
    }
}

// ---------------- pipelined fp16 GEMM (phase 1):  C = A@B^T + bias ----------
#define ASTG_B 16384
#define STGB   (2 * ASTG_B)
#define GEMM_SMEM (3 * STGB)      // 98304 B
__global__ __launch_bounds__(256, 2)
void gemm_h(const __half* __restrict__ A, const __half* __restrict__ B,
            float* __restrict__ C, const float* __restrict__ bias,
            const int* __restrict__ gidx,
            int M, int N, int K, int lda, int GROUPM)
{
    extern __shared__ char smem[];
    const uint32_t sb = (uint32_t)__cvta_generic_to_shared(smem);
    __shared__ int sidx[128];

    const int grid_m = M >> 7, grid_n = N >> 7;
    const int pid = blockIdx.x;
    const int width = GROUPM * grid_n;
    const int grp = pid / width;
    const int first = grp * GROUPM;
    const int gsz = min(grid_m - first, GROUPM);
    const int pm = first + (pid % width) % gsz;
    const int pn = (pid % width) / gsz;
    const int m0 = pm << 7, n0 = pn << 7;

    const int tid = threadIdx.x, lane = tid & 31, wid = tid >> 5;
    const int wm = (wid & 1) << 6;
    const int wn = (wid >> 1) << 5;

    if (tid < 128) sidx[tid] = gidx ? gidx[m0 + tid] : (m0 + tid);
    __syncthreads();

    const int NCH = K >> 6;

    auto load_stage = [&](int st, int kt) {
        uint32_t stb = sb + (uint32_t)st * STGB;
#pragma unroll
        for (int i = 0; i < 4; i++) {
            int l = tid + (i << 8);
            int r = l >> 3, c8 = (l & 7) << 3;
            cp16(stb + swz(r, c8, 128), A + (size_t)sidx[r] * lda + kt + c8);
            cp16(stb + ASTG_B + swz(r, c8, 128), B + (size_t)(n0 + r) * K + kt + c8);
        }
    };

    float acc[4][4][4];
#pragma unroll
    for (int i = 0; i < 4; i++)
#pragma unroll
        for (int j = 0; j < 4; j++)
#pragma unroll
            for (int q = 0; q < 4; q++) acc[i][j][q] = 0.f;

    load_stage(0, 0); cp_commit();
    if (NCH > 1) load_stage(1, 64);
    cp_commit();

    const int mm = lane >> 3, r8 = lane & 7;
    for (int it = 0; it < NCH; it++) {
        if (it + 2 < NCH) load_stage((it + 2) % 3, (it + 2) << 6);
        cp_commit();
        cp_wait<2>();
        __syncthreads();

        uint32_t Ab = sb + (uint32_t)(it % 3) * STGB;
        uint32_t Bb = Ab + ASTG_B;
#pragma unroll
        for (int ks = 0; ks < 4; ks++) {
            uint32_t af[4][4], bf[4][2];
#pragma unroll
            for (int fm = 0; fm < 4; fm++) {
                int row = wm + (fm << 4) + r8 + ((mm & 1) << 3);
                int ko = (ks << 4) + ((mm >> 1) << 3);
                ldm_x4(af[fm], Ab + swz(row, ko, 128));
            }
#pragma unroll
            for (int h = 0; h < 2; h++) {
                uint32_t t4[4];
                int col = wn + (h << 4) + ((mm >> 1) << 3) + r8;
                int ko = (ks << 4) + ((mm & 1) << 3);
                ldm_x4(t4, Bb + swz(col, ko, 128));
                bf[h * 2][0] = t4[0]; bf[h * 2][1] = t4[1];
                bf[h * 2 + 1][0] = t4[2]; bf[h * 2 + 1][1] = t4[3];
            }
#pragma unroll
            for (int fm = 0; fm < 4; fm++)
#pragma unroll
                for (int fn = 0; fn < 4; fn++)
                    mma16(acc[fm][fn], af[fm], bf[fn]);
        }
        __syncthreads();
    }

    const int c2 = (lane & 3) << 1;
#pragma unroll
    for (int fm = 0; fm < 4; fm++) {
        int r = m0 + wm + (fm << 4) + (lane >> 2);
#pragma unroll
        for (int fn = 0; fn < 4; fn++) {
            int c = n0 + wn + (fn << 3) + c2;
            float b0 = bias[c], b1 = bias[c + 1];
            float2 v0 = make_float2(acc[fm][fn][0] + b0, acc[fm][fn][1] + b1);
            float2 v1 = make_float2(acc[fm][fn][2] + b0, acc[fm][fn][3] + b1);
            *(float2*)(C + (size_t)r * N + c) = v0;
            *(float2*)(C + (size_t)(r + 8) * N + c) = v1;
        }
    }
}

// ---------------- MEGA kernel: LSTM (blocks 0..63) + phase-3 tile pool ------
// 1 block/SM guaranteed by smem footprint -> all blocks co-resident.
// LSTM role: 512 threads, paired-warp K split (warps w / w+8 halve K),
// W_hh slice (64 gate-rows x 1024) resident in swizzled smem; after step t
// completes (global sw barrier over 64 blocks), block 0 publishes g_prog=t+1.
// GEMM role: persistent work-stealing over 8000 tiles (BM=128, BN=256,
// BK=64, 3-stage cp.async); tile mt gated on g_prog >= 2mt+2. mt-major order.
#define LW_B    131072            // 64 rows x 2048 B
#define LA_B    32768             // h stage: 64 rows x 512 B
#define MG_ASTG 16384             // gemm A stage
#define MG_BSTG 32768             // gemm B stage
#define MG_STG  (MG_ASTG + MG_BSTG)
#define MEGA_SMEM (LW_B + 2 * LA_B + 64 * 68 * 4)   // 214016 B (>= 3*MG_STG)

__global__ __launch_bounds__(512, 1)
void mega_k(float* __restrict__ out, const float* __restrict__ lin_b)
{
    extern __shared__ char smem[];
    const uint32_t sb = (uint32_t)__cvta_generic_to_shared(smem);
    const int tid = threadIdx.x, lane = tid & 31, wid = tid >> 5;
    const int mm = lane >> 3, r8 = lane & 7;

    if (blockIdx.x < 64) {
        // ================= LSTM role =================
        const uint32_t bwb = sb, ab = sb + LW_B;
        float* Gs = (float*)(smem + LW_B + 2 * LA_B);
        const int u0 = (int)blockIdx.x << 4;      // 16 units
        const int wc = (wid & 7) << 3;            // 8 gate-cols per warp pair
        const int ksb = (wid >> 3) << 3;          // K-split: 0 or 8
        const int sel = mm & 1;

        for (int idx = tid; idx < 64 * 128; idx += 512) {
            int r = idx >> 7, c8 = (idx & 127) << 3;
            int grow = ((r >> 4) << 10) + u0 + (r & 15);
            cp16(bwb + swz(r, c8, 2048), g_WhhTh + (size_t)grow * HID + c8);
        }
        cp_commit(); cp_wait<0>();
        __syncthreads();

        for (int t = 0; t < SEQL; t++) {
            const __half* hp = t ? (g_hidh + (size_t)(t - 1) * BATCH * HID) : g_h0h;
            float acc[4][4];
#pragma unroll
            for (int i = 0; i < 4; i++)
#pragma unroll
                for (int q = 0; q < 4; q++) acc[i][q] = 0.f;

            auto loadA = [&](int st, int kc) {
#pragma unroll
                for (int i = 0; i < 4; i++) {
                    int l = tid + (i << 9);
                    int r = l >> 5, c8 = (l & 31) << 3;
                    cp16(ab + (uint32_t)st * LA_B + swz(r, c8, 512),
                         hp + (size_t)r * HID + kc + c8);
                }
            };

            loadA(0, 0); cp_commit();
            for (int ch = 0; ch < 4; ch++) {
                if (ch < 3) { loadA((ch + 1) & 1, (ch + 1) << 8); cp_commit(); cp_wait<1>(); }
                else         cp_wait<0>();
                __syncthreads();
                uint32_t Ab = ab + (uint32_t)(ch & 1) * LA_B;
                const int kb = ch << 8;
#pragma unroll
                for (int ks = 0; ks < 8; ks++) {
                    const int kk = ksb + ks;
                    uint32_t af[4][4], bf[2];
#pragma unroll
                    for (int fm = 0; fm < 4; fm++) {
                        int row = (fm << 4) + r8 + ((mm & 1) << 3);
                        int ko = (kk << 4) + ((mm >> 1) << 3);
                        ldm_x4(af[fm], Ab + swz(row, ko, 512));
                    }
                    ldm_x2(bf, bwb + swz(wc + r8, kb + (kk << 4) + (sel << 3), 2048));
#pragma unroll
                    for (int fm = 0; fm < 4; fm++) mma16(acc[fm], af[fm], bf);
                }
                __syncthreads();
            }

            const int c2l = (lane & 3) << 1;
            if (wid < 8) {
#pragma unroll
                for (int fm = 0; fm < 4; fm++) {
                    int r = (fm << 4) + (lane >> 2), c = wc + c2l;
                    Gs[r * 68 + c]           = acc[fm][0];
                    Gs[r * 68 + c + 1]       = acc[fm][1];
                    Gs[(r + 8) * 68 + c]     = acc[fm][2];
                    Gs[(r + 8) * 68 + c + 1] = acc[fm][3];
                }
            }
            __syncthreads();
            if (wid >= 8) {
#pragma unroll
                for (int fm = 0; fm < 4; fm++) {
                    int r = (fm << 4) + (lane >> 2), c = wc + c2l;
                    Gs[r * 68 + c]           += acc[fm][0];
                    Gs[r * 68 + c + 1]       += acc[fm][1];
                    Gs[(r + 8) * 68 + c]     += acc[fm][2];
                    Gs[(r + 8) * 68 + c + 1] += acc[fm][3];
                }
            }
            __syncthreads();

#pragma unroll
            for (int i = 0; i < 2; i++) {
                int p = tid + (i << 9);
                int row = p >> 4, u = p & 15;
                size_t xb = ((size_t)(t * BATCH + row)) * G4 + u0 + u;
                float gi = Gs[row * 68 + u]      + g_xg[xb];
                float gf = Gs[row * 68 + 16 + u] + g_xg[xb + HID];
                float gg = Gs[row * 68 + 32 + u] + g_xg[xb + 2 * HID];
                float go = Gs[row * 68 + 48 + u] + g_xg[xb + 3 * HID];
                float iv = sigmoidf_(gi);
                float fv = sigmoidf_(gf);
                float gv = tanhf(gg);
                float ov = sigmoidf_(go);
                int ci = row * HID + u0 + u;
                float cv = fv * g_c[ci] + iv * gv;
                g_c[ci] = cv;
                g_hidh[(size_t)(t * BATCH + row) * HID + u0 + u] =
                    __float2half_rn(ov * tanhf(cv));
            }

            __threadfence();
            __syncthreads();
            if (tid == 0) {
                atomicAdd(&g_bar[t], 1);
                while (*(volatile int*)&g_bar[t] < 64) __nanosleep(32);
                if (blockIdx.x == 0) atomicExch(&g_prog, t + 1);
            }
            __syncthreads();
        }
        __syncthreads();
    }

    // ================= GEMM pool role =================
    const int wm = (wid & 1) << 6;
    const int wn = (wid >> 1) << 5;
    __shared__ int s_id;

    for (;;) {
        if (tid == 0) s_id = atomicAdd(&g_tile, 1);
        __syncthreads();
        const int id = s_id;
        if (id >= NTILE) break;
        const int mt = id / NT_N, nt = id - mt * NT_N;
        const int m0 = mt << 7, n0 = nt << 8;

        if (tid == 0) {
            while (*(volatile int*)&g_prog < 2 * mt + 2) __nanosleep(128);
        }
        __syncthreads();
        __threadfence();

        auto load_stage = [&](int st, int kt) {
            uint32_t stb = sb + (uint32_t)st * MG_STG;
#pragma unroll
            for (int i = 0; i < 2; i++) {
                int l = tid + (i << 9);
                int r = l >> 3, c8 = (l & 7) << 3;
                cp16(stb + swz(r, c8, 128), g_hidh + (size_t)(m0 + r) * HID + kt + c8);
            }
#pragma unroll
            for (int i = 0; i < 4; i++) {
                int l = tid + (i << 9);
                int r = l >> 3, c8 = (l & 7) << 3;
                cp16(stb + MG_ASTG + swz(r, c8, 128),
                     g_linWh + (size_t)(n0 + r) * HID + kt + c8);
            }
        };

        float acc[4][4][4];
#pragma unroll
        for (int i = 0; i < 4; i++)
#pragma unroll
            for (int j = 0; j < 4; j++)
#pragma unroll
                for (int q = 0; q < 4; q++) acc[i][j][q] = 0.f;

        load_stage(0, 0); cp_commit();
        load_stage(1, 64); cp_commit();

        for (int it = 0; it < 16; it++) {
            if (it + 2 < 16) load_stage((it + 2) % 3, (it + 2) << 6);
            cp_commit();
            cp_wait<2>();
            __syncthreads();

            uint32_t Ab = sb + (uint32_t)(it % 3) * MG_STG;
            uint32_t Bb = Ab + MG_ASTG;
#pragma unroll
            for (int ks = 0; ks < 4; ks++) {
                uint32_t af[4][4], bf[4][2];
#pragma unroll
                for (int fm = 0; fm < 4; fm++) {
                    int row = wm + (fm << 4) + r8 + ((mm & 1) << 3);
                    int ko = (ks << 4) + ((mm >> 1) << 3);
                    ldm_x4(af[fm], Ab + swz(row, ko, 128));
                }
#pragma unroll
                for (int h = 0; h < 2; h++) {
                    uint32_t t4[4];
                    int col = wn + (h << 4) + ((mm >> 1) << 3) + r8;
                    int ko = (ks << 4) + ((mm & 1) << 3);
                    ldm_x4(t4, Bb + swz(col, ko, 128));
                    bf[h * 2][0] = t4[0]; bf[h * 2][1] = t4[1];
                    bf[h * 2 + 1][0] = t4[2]; bf[h * 2 + 1][1] = t4[3];
                }
#pragma unroll
                for (int fm = 0; fm < 4; fm++)
#pragma unroll
                    for (int fn = 0; fn < 4; fn++)
                        mma16(acc[fm][fn], af[fm], bf[fn]);
            }
            __syncthreads();
        }

        const int c2 = (lane & 3) << 1;
#pragma unroll
        for (int fm = 0; fm < 4; fm++) {
            int r = m0 + wm + (fm << 4) + (lane >> 2);
#pragma unroll
            for (int fn = 0; fn < 4; fn++) {
                int c = n0 + wn + (fn << 3) + c2;
                float b0 = lin_b[c], b1 = lin_b[c + 1];
                float2 v0 = make_float2(acc[fm][fn][0] + b0, acc[fm][fn][1] + b1);
                float2 v1 = make_float2(acc[fm][fn][2] + b0, acc[fm][fn][3] + b1);
                *(float2*)(out + (size_t)r * VOCAB + c) = v0;
                *(float2*)(out + (size_t)(r + 8) * VOCAB + c) = v1;
            }
        }
        __syncthreads();
    }
}

// ---------------- launch -----------------------------------------------------
extern "C" void kernel_launch(void* const* d_in, const int* in_sizes, int n_in,
                              void* d_out, int out_size)
{
    const int*   input  = (const int*)d_in[0];
    const float* emb    = (const float*)d_in[1];
    const float* W_ih   = (const float*)d_in[2];
    const float* W_hh   = (const float*)d_in[3];
    const float* b_lstm = (const float*)d_in[4];
    const float* lin_W  = (const float*)d_in[5];
    const float* lin_b  = (const float*)d_in[6];
    const float* h0     = (const float*)d_in[7];
    const float* c0     = (const float*)d_in[8];
    float* out = (float*)d_out;

    float  *p_xg;
    __half *p_embh, *p_linWh, *p_wihTh;
    cudaGetSymbolAddress((void**)&p_xg, g_xg);
    cudaGetSymbolAddress((void**)&p_embh, g_embh);
    cudaGetSymbolAddress((void**)&p_linWh, g_linWh);
    cudaGetSymbolAddress((void**)&p_wihTh, g_WihTh);

    int nsm = 148;
    cudaDeviceGetAttribute(&nsm, cudaDevAttrMultiProcessorCount, 0);
    if (nsm < 66) nsm = 66;   // safety: need >64 resident blocks

    cudaFuncSetAttribute(gemm_h, cudaFuncAttributeMaxDynamicSharedMemorySize, GEMM_SMEM);
    cudaFuncSetAttribute(mega_k, cudaFuncAttributeMaxDynamicSharedMemorySize, MEGA_SMEM);

    cvt_k<<<(VOCAB * EMB / 4 + 255) / 256, 256>>>(emb, p_embh, VOCAB * EMB / 4);
    cvt_k<<<(VOCAB * HID / 4 + 255) / 256, 256>>>(lin_W, p_linWh, VOCAB * HID / 4);
    transpose_cvt_k<<<dim3(G4 / 32, EMB / 32), dim3(32, 8)>>>(W_ih, EMB, G4, 0);
    transpose_cvt_k<<<dim3(G4 / 32, HID / 32), dim3(32, 8)>>>(W_hh, HID, G4, 1);
    init_k<<<(BATCH * HID + 255) / 256, 256>>>(c0, h0);

    // Phase 1: xg = gather(emb, input) @ W_ih + b_lstm   (M=8192,N=4096,K=512)
    gemm_h<<<(MTOT / 128) * (G4 / 128), 256, GEMM_SMEM>>>(
        p_embh, p_wihTh, p_xg, b_lstm, input, MTOT, G4, EMB, EMB, 16);

    // Phase 2+3 fused: LSTM (blocks 0..63) overlapped with logits GEMM pool
    mega_k<<<nsm, 512, MEGA_SMEM>>>(out, lin_b);

    // Phase 4: append h_T, c_T after logits
    tail_k<<<(BATCH * HID + 255) / 256, 256>>>(out);
}

// round 13
// speedup vs baseline: 5.0003x; 1.0683x over previous
#include <cuda_runtime.h>
#include <cuda_fp16.h>
#include <cstdint>

#define SEQL  128
#define BATCH 64
#define EMB   512
#define HID   1024
#define VOCAB 32000
#define G4    4096      // 4*HID
#define MTOT  8192      // SEQL*BATCH
#define NT_N  125       // 32000 / 256
#define NT1   1024      // phase-1 tiles: 64 mt x 16 nt  (BM=128, BN=256)
#define NTILE (NT1 + 64 * NT_N)

// ---------------- scratch (device globals) ----------------------------------
__device__ __align__(128) float  g_xg[(size_t)MTOT * G4];      // 134 MB fp32
__device__ __align__(128) __half g_hidh[(size_t)MTOT * HID];   // 16 MB
__device__ __align__(128) __half g_embh[(size_t)VOCAB * EMB];  // 32 MB
__device__ __align__(128) __half g_linWh[(size_t)VOCAB * HID]; // 65 MB
__device__ __align__(128) __half g_WihTh[(size_t)G4 * EMB];    // 4 MB
__device__ __align__(128) __half g_WhhTh[(size_t)G4 * HID];    // 8 MB
__device__ __align__(128) __half g_h0h[BATCH * HID];
__device__ __align__(128) float  g_c[BATCH * HID];
__device__ int g_bar[SEQL];
__device__ int g_xg_done[64];     // per xg m-tile: # of completed n-tiles (16)
__device__ int g_prog;
__device__ int g_tile;

// ---------------- helpers ---------------------------------------------------
__device__ __forceinline__ void mma16(float* d, const uint32_t* a, const uint32_t* b) {
    asm volatile(
        "mma.sync.aligned.m16n8k16.row.col.f32.f16.f16.f32 "
        "{%0,%1,%2,%3}, {%4,%5,%6,%7}, {%8,%9}, {%0,%1,%2,%3};"
        : "+f"(d[0]), "+f"(d[1]), "+f"(d[2]), "+f"(d[3])
        : "r"(a[0]), "r"(a[1]), "r"(a[2]), "r"(a[3]), "r"(b[0]), "r"(b[1]));
}

__device__ __forceinline__ void ldm_x4(uint32_t* d, uint32_t addr) {
    asm volatile("ldmatrix.sync.aligned.m8n8.x4.shared.b16 {%0,%1,%2,%3}, [%4];"
        : "=r"(d[0]), "=r"(d[1]), "=r"(d[2]), "=r"(d[3]) : "r"(addr));
}
__device__ __forceinline__ void ldm_x2(uint32_t* d, uint32_t addr) {
    asm volatile("ldmatrix.sync.aligned.m8n8.x2.shared.b16 {%0,%1}, [%2];"
        : "=r"(d[0]), "=r"(d[1]) : "r"(addr));
}

__device__ __forceinline__ float sigmoidf_(float x) {
    return 1.0f / (1.0f + __expf(-x));
}

__device__ __forceinline__ void cp16(uint32_t dst, const void* src) {
    asm volatile("cp.async.cg.shared.global [%0], [%1], 16;" :: "r"(dst), "l"(src));
}
__device__ __forceinline__ void cp_commit() {
    asm volatile("cp.async.commit_group;");
}
template <int N>
__device__ __forceinline__ void cp_wait() {
    asm volatile("cp.async.wait_group %0;" :: "n"(N));
}

// XOR-swizzled smem byte offset for row r, half-offset ho within the row.
__device__ __forceinline__ uint32_t swz(uint32_t r, uint32_t ho, uint32_t rowbytes) {
    uint32_t b = ho << 1;
    uint32_t grp = b & ~127u;
    uint32_t ci = (b >> 4) & 7u;
    return r * rowbytes + grp + (((ci ^ (r & 7u)) << 4) | (b & 15u));
}

// ---------------- conversion / init / transpose / tail ----------------------
__global__ void cvt_k(const float* __restrict__ in, __half* __restrict__ out, int n4) {
    int i = blockIdx.x * blockDim.x + threadIdx.x;
    if (i < n4) {
        float4 v = *(const float4*)(in + (size_t)i * 4);
        __half2* o = (__half2*)(out + (size_t)i * 4);
        o[0] = __floats2half2_rn(v.x, v.y);
        o[1] = __floats2half2_rn(v.z, v.w);
    }
}

__global__ void init_k(const float* __restrict__ c0, const float* __restrict__ h0) {
    int i = blockIdx.x * blockDim.x + threadIdx.x;
    if (i < BATCH * HID) {
        g_c[i] = c0[i];
        g_h0h[i] = __float2half_rn(h0[i]);
    }
    if (i < SEQL) g_bar[i] = 0;
    if (i < 64) g_xg_done[i] = 0;
    if (i == 0) { g_prog = 0; g_tile = 0; }
}

// in: R x C fp32 row-major -> out: C x R half row-major
__global__ void transpose_cvt_k(const float* __restrict__ in, int R, int C, int which) {
    __shared__ float tmp[32][33];
    __half* out = which ? g_WhhTh : g_WihTh;
    int cb = blockIdx.x << 5, rb = blockIdx.y << 5;
    int x = threadIdx.x, y = threadIdx.y;
#pragma unroll
    for (int i = 0; i < 32; i += 8)
        tmp[y + i][x] = in[(size_t)(rb + y + i) * C + cb + x];
    __syncthreads();
#pragma unroll
    for (int i = 0; i < 32; i += 8)
        out[(size_t)(cb + y + i) * R + rb + x] = __float2half_rn(tmp[x][y + i]);
}

__global__ void tail_k(float* __restrict__ out) {
    int i = blockIdx.x * blockDim.x + threadIdx.x;
    if (i < BATCH * HID) {
        const size_t LOG = (size_t)MTOT * VOCAB;
        out[LOG + i] = __half2float(g_hidh[(size_t)(SEQL - 1) * BATCH * HID + i]);
        out[LOG + (size_t)BATCH * HID + i] = g_c[i];
    }
}

// ---------------- MEGA kernel ------------------------------------------------
// Blocks 0..63: LSTM recurrence (W_hh slice resident in smem), step t gated on
// xg row availability (g_xg_done), publishes g_prog. Then join tile pool.
// All other blocks: work-stealing tile pool. Pool ids [0,1024): phase-1 tiles
// (xg = gather(emb) @ W_ihT + b_lstm, K=512, 64 mt x 16 nt, mt-major so rows
// complete in order), completion feeds g_xg_done. Ids [1024,9024): phase-3
// logits tiles, gated on g_prog >= 2*mt+2.
// Pool GEMM: BM=128, BN=256, BK=64, 512 thr, 4-stage cp.async, 1 sync/chunk.
#define LW_B    131072            // 64 rows x 2048 B
#define LA_B    32768             // h stage: 64 rows x 512 B
#define MG_ASTG 16384
#define MG_BSTG 32768
#define MG_STG  (MG_ASTG + MG_BSTG)
#define MEGA_SMEM (LW_B + 2 * LA_B + 64 * 68 * 4)   // 214016 B (>= 4*MG_STG)

// One BM=128 x BN=256 tile, K=Kd (multiple of 64). A rows via sidx gather.
// Both A and B have leading dim = Kd. Entry __syncthreads makes the freshly
// written sidx visible to all 512 threads AND separates this tile's stage-0
// writes from the previous tile's last-stage reads.
__device__ __forceinline__ void pool_tile(
    uint32_t sb, const __half* __restrict__ A, const __half* __restrict__ Bm,
    float* __restrict__ C, const float* __restrict__ bias,
    int n0, int Kd, int ldc, int m0out, const int* sidx)
{
    __syncthreads();

    const int tid = threadIdx.x, lane = tid & 31, wid = tid >> 5;
    const int mm = lane >> 3, r8 = lane & 7;
    const int wm = (wid & 1) << 6;
    const int wn = (wid >> 1) << 5;
    const int NCH = Kd >> 6;

    auto load_stage = [&](int st, int kt) {
        uint32_t stb = sb + (uint32_t)st * MG_STG;
#pragma unroll
        for (int i = 0; i < 2; i++) {
            int l = tid + (i << 9);
            int r = l >> 3, c8 = (l & 7) << 3;
            cp16(stb + swz(r, c8, 128), A + (size_t)sidx[r] * Kd + kt + c8);
        }
#pragma unroll
        for (int i = 0; i < 4; i++) {
            int l = tid + (i << 9);
            int r = l >> 3, c8 = (l & 7) << 3;
            cp16(stb + MG_ASTG + swz(r, c8, 128), Bm + (size_t)(n0 + r) * Kd + kt + c8);
        }
    };

    float acc[4][4][4];
#pragma unroll
    for (int i = 0; i < 4; i++)
#pragma unroll
        for (int j = 0; j < 4; j++)
#pragma unroll
            for (int q = 0; q < 4; q++) acc[i][j][q] = 0.f;

    load_stage(0, 0); cp_commit();
    load_stage(1, 64); cp_commit();

    for (int it = 0; it < NCH; it++) {
        if (it + 2 < NCH) load_stage((it + 2) & 3, (it + 2) << 6);
        cp_commit();
        cp_wait<2>();
        __syncthreads();

        uint32_t Ab = sb + (uint32_t)(it & 3) * MG_STG;
        uint32_t Bb = Ab + MG_ASTG;
#pragma unroll
        for (int ks = 0; ks < 4; ks++) {
            uint32_t af[4][4], bf[4][2];
#pragma unroll
            for (int fm = 0; fm < 4; fm++) {
                int row = wm + (fm << 4) + r8 + ((mm & 1) << 3);
                int ko = (ks << 4) + ((mm >> 1) << 3);
                ldm_x4(af[fm], Ab + swz(row, ko, 128));
            }
#pragma unroll
            for (int h = 0; h < 2; h++) {
                uint32_t t4[4];
                int col = wn + (h << 4) + ((mm >> 1) << 3) + r8;
                int ko = (ks << 4) + ((mm & 1) << 3);
                ldm_x4(t4, Bb + swz(col, ko, 128));
                bf[h * 2][0] = t4[0]; bf[h * 2][1] = t4[1];
                bf[h * 2 + 1][0] = t4[2]; bf[h * 2 + 1][1] = t4[3];
            }
#pragma unroll
            for (int fm = 0; fm < 4; fm++)
#pragma unroll
                for (int fn = 0; fn < 4; fn++)
                    mma16(acc[fm][fn], af[fm], bf[fn]);
        }
    }

    const int c2 = (lane & 3) << 1;
#pragma unroll
    for (int fm = 0; fm < 4; fm++) {
        int r = m0out + wm + (fm << 4) + (lane >> 2);
#pragma unroll
        for (int fn = 0; fn < 4; fn++) {
            int c = n0 + wn + (fn << 3) + c2;
            float b0 = bias[c], b1 = bias[c + 1];
            float2 v0 = make_float2(acc[fm][fn][0] + b0, acc[fm][fn][1] + b1);
            float2 v1 = make_float2(acc[fm][fn][2] + b0, acc[fm][fn][3] + b1);
            *(float2*)(C + (size_t)r * ldc + c) = v0;
            *(float2*)(C + (size_t)(r + 8) * ldc + c) = v1;
        }
    }
}

__global__ __launch_bounds__(512, 1)
void mega_k(float* __restrict__ out, const float* __restrict__ lin_b,
            const float* __restrict__ b_lstm, const int* __restrict__ input)
{
    extern __shared__ char smem[];
    const uint32_t sb = (uint32_t)__cvta_generic_to_shared(smem);
    const int tid = threadIdx.x, lane = tid & 31, wid = tid >> 5;
    const int mm = lane >> 3, r8 = lane & 7;
    __shared__ int s_id;
    __shared__ int sidx[128];

    if (blockIdx.x < 64) {
        // ================= LSTM role =================
        const uint32_t bwb = sb, ab = sb + LW_B;
        float* Gs = (float*)(smem + LW_B + 2 * LA_B);
        const int u0 = (int)blockIdx.x << 4;      // 16 units
        const int wc = (wid & 7) << 3;
        const int ksb = (wid >> 3) << 3;
        const int sel = mm & 1;

        for (int idx = tid; idx < 64 * 128; idx += 512) {
            int r = idx >> 7, c8 = (idx & 127) << 3;
            int grow = ((r >> 4) << 10) + u0 + (r & 15);
            cp16(bwb + swz(r, c8, 2048), g_WhhTh + (size_t)grow * HID + c8);
        }
        cp_commit(); cp_wait<0>();
        __syncthreads();

        for (int t = 0; t < SEQL; t++) {
            // wait for xg rows of this timestep (phase-1 pool tiles)
            if (tid == 0) {
                while (*(volatile int*)&g_xg_done[t >> 1] < 16) __nanosleep(64);
            }
            __syncthreads();
            __threadfence();

            const __half* hp = t ? (g_hidh + (size_t)(t - 1) * BATCH * HID) : g_h0h;
            float acc[4][4];
#pragma unroll
            for (int i = 0; i < 4; i++)
#pragma unroll
                for (int q = 0; q < 4; q++) acc[i][q] = 0.f;

            auto loadA = [&](int st, int kc) {
#pragma unroll
                for (int i = 0; i < 4; i++) {
                    int l = tid + (i << 9);
                    int r = l >> 5, c8 = (l & 31) << 3;
                    cp16(ab + (uint32_t)st * LA_B + swz(r, c8, 512),
                         hp + (size_t)r * HID + kc + c8);
                }
            };

            loadA(0, 0); cp_commit();
            for (int ch = 0; ch < 4; ch++) {
                if (ch < 3) { loadA((ch + 1) & 1, (ch + 1) << 8); cp_commit(); cp_wait<1>(); }
                else         cp_wait<0>();
                __syncthreads();
                uint32_t Ab = ab + (uint32_t)(ch & 1) * LA_B;
                const int kb = ch << 8;
#pragma unroll
                for (int ks = 0; ks < 8; ks++) {
                    const int kk = ksb + ks;
                    uint32_t af[4][4], bf[2];
#pragma unroll
                    for (int fm = 0; fm < 4; fm++) {
                        int row = (fm << 4) + r8 + ((mm & 1) << 3);
                        int ko = (kk << 4) + ((mm >> 1) << 3);
                        ldm_x4(af[fm], Ab + swz(row, ko, 512));
                    }
                    ldm_x2(bf, bwb + swz(wc + r8, kb + (kk << 4) + (sel << 3), 2048));
#pragma unroll
                    for (int fm = 0; fm < 4; fm++) mma16(acc[fm], af[fm], bf);
                }
                __syncthreads();
            }

            const int c2l = (lane & 3) << 1;
            if (wid < 8) {
#pragma unroll
                for (int fm = 0; fm < 4; fm++) {
                    int r = (fm << 4) + (lane >> 2), c = wc + c2l;
                    Gs[r * 68 + c]           = acc[fm][0];
                    Gs[r * 68 + c + 1]       = acc[fm][1];
                    Gs[(r + 8) * 68 + c]     = acc[fm][2];
                    Gs[(r + 8) * 68 + c + 1] = acc[fm][3];
                }
            }
            __syncthreads();
            if (wid >= 8) {
#pragma unroll
                for (int fm = 0; fm < 4; fm++) {
                    int r = (fm << 4) + (lane >> 2), c = wc + c2l;
                    Gs[r * 68 + c]           += acc[fm][0];
                    Gs[r * 68 + c + 1]       += acc[fm][1];
                    Gs[(r + 8) * 68 + c]     += acc[fm][2];
                    Gs[(r + 8) * 68 + c + 1] += acc[fm][3];
                }
            }
            __syncthreads();

#pragma unroll
            for (int i = 0; i < 2; i++) {
                int p = tid + (i << 9);
                int row = p >> 4, u = p & 15;
                size_t xb = ((size_t)(t * BATCH + row)) * G4 + u0 + u;
                float gi = Gs[row * 68 + u]      + g_xg[xb];
                float gf = Gs[row * 68 + 16 + u] + g_xg[xb + HID];
                float gg = Gs[row * 68 + 32 + u] + g_xg[xb + 2 * HID];
                float go = Gs[row * 68 + 48 + u] + g_xg[xb + 3 * HID];
                float iv = sigmoidf_(gi);
                float fv = sigmoidf_(gf);
                float gv = tanhf(gg);
                float ov = sigmoidf_(go);
                int ci = row * HID + u0 + u;
                float cv = fv * g_c[ci] + iv * gv;
                g_c[ci] = cv;
                g_hidh[(size_t)(t * BATCH + row) * HID + u0 + u] =
                    __float2half_rn(ov * tanhf(cv));
            }

            __threadfence();
            __syncthreads();
            if (tid == 0) {
                atomicAdd(&g_bar[t], 1);
                while (*(volatile int*)&g_bar[t] < 64) __nanosleep(32);
                if (blockIdx.x == 0) atomicExch(&g_prog, t + 1);
            }
            __syncthreads();
        }
        __syncthreads();
    }

    // ================= tile pool role =================
    for (;;) {
        if (tid == 0) s_id = atomicAdd(&g_tile, 1);
        __syncthreads();
        const int id = s_id;
        if (id >= NTILE) break;

        if (id < NT1) {
            // phase-1: xg tile. mt-major (nt fastest) so rows finish in order.
            const int mt = id >> 4, nt = id & 15;
            const int m0 = mt << 7, n0 = nt << 8;
            if (tid < 128) sidx[tid] = input[m0 + tid];
            pool_tile(sb, g_embh, g_WihTh, g_xg, b_lstm, n0, EMB, G4, m0, sidx);
            __threadfence();
            __syncthreads();
            if (tid == 0) atomicAdd(&g_xg_done[mt], 1);
        } else {
            // phase-3: logits tile, gated on LSTM progress.
            const int id3 = id - NT1;
            const int mt = id3 / NT_N, nt = id3 - mt * NT_N;
            const int m0 = mt << 7, n0 = nt << 8;
            if (tid == 0) {
                while (*(volatile int*)&g_prog < 2 * mt + 2) __nanosleep(128);
            }
            __syncthreads();
            __threadfence();
            if (tid < 128) sidx[tid] = m0 + tid;
            pool_tile(sb, g_hidh, g_linWh, out, lin_b, n0, HID, VOCAB, m0, sidx);
            __syncthreads();
        }
    }
}

// ---------------- launch -----------------------------------------------------
extern "C" void kernel_launch(void* const* d_in, const int* in_sizes, int n_in,
                              void* d_out, int out_size)
{
    const int*   input  = (const int*)d_in[0];
    const float* emb    = (const float*)d_in[1];
    const float* W_ih   = (const float*)d_in[2];
    const float* W_hh   = (const float*)d_in[3];
    const float* b_lstm = (const float*)d_in[4];
    const float* lin_W  = (const float*)d_in[5];
    const float* lin_b  = (const float*)d_in[6];
    const float* h0     = (const float*)d_in[7];
    const float* c0     = (const float*)d_in[8];
    float* out = (float*)d_out;

    __half *p_embh, *p_linWh;
    cudaGetSymbolAddress((void**)&p_embh, g_embh);
    cudaGetSymbolAddress((void**)&p_linWh, g_linWh);

    int nsm = 148;
    cudaDeviceGetAttribute(&nsm, cudaDevAttrMultiProcessorCount, 0);
    if (nsm < 66) nsm = 66;   // need >64 resident blocks for pool progress

    cudaFuncSetAttribute(mega_k, cudaFuncAttributeMaxDynamicSharedMemorySize, MEGA_SMEM);

    cvt_k<<<(VOCAB * EMB / 4 + 255) / 256, 256>>>(emb, p_embh, VOCAB * EMB / 4);
    cvt_k<<<(VOCAB * HID / 4 + 255) / 256, 256>>>(lin_W, p_linWh, VOCAB * HID / 4);
    transpose_cvt_k<<<dim3(G4 / 32, EMB / 32), dim3(32, 8)>>>(W_ih, EMB, G4, 0);
    transpose_cvt_k<<<dim3(G4 / 32, HID / 32), dim3(32, 8)>>>(W_hh, HID, G4, 1);
    init_k<<<(BATCH * HID + 255) / 256, 256>>>(c0, h0);

    // Fused: phase-1 tile pool + LSTM recurrence + phase-3 tile pool
    mega_k<<<nsm, 512, MEGA_SMEM>>>(out, lin_b, b_lstm, input);

    // append h_T, c_T after logits
    tail_k<<<(BATCH * HID + 255) / 256, 256>>>(out);
}

// round 14
// speedup vs baseline: 5.0477x; 1.0095x over previous
#include <cuda_runtime.h>
#include <cuda_fp16.h>
#include <cstdint>

#define SEQL  128
#define BATCH 64
#define EMB   512
#define HID   1024
#define VOCAB 32000
#define G4    4096      // 4*HID
#define MTOT  8192      // SEQL*BATCH
#define NT_N  125       // 32000 / 256
#define NT1   1024      // phase-1 tiles: 64 mt x 16 nt (BM=128, BN=256)
#define NT1A  64        // first p1 batch (mt 0..3) before cvtW tiles
#define NCVW  125       // lin_W convert tiles (256 rows each)
#define NTILE (NT1 + NCVW + 64 * NT_N)   // 9149

// ---------------- scratch (device globals) ----------------------------------
__device__ __align__(128) __half g_xgh[(size_t)MTOT * G4];     // 67 MB fp16
__device__ __align__(128) __half g_hidh[(size_t)MTOT * HID];   // 16 MB
__device__ __align__(128) __half g_embh[(size_t)VOCAB * EMB];  // 32 MB
__device__ __align__(128) __half g_linWh[(size_t)VOCAB * HID]; // 65 MB
__device__ __align__(128) __half g_WihTh[(size_t)G4 * EMB];    // 4 MB
__device__ __align__(128) __half g_WhhTh[(size_t)G4 * HID];    // 8 MB
__device__ __align__(128) __half g_h0h[BATCH * HID];
__device__ __align__(128) float  g_c[BATCH * HID];
__device__ int g_bar[SEQL];
__device__ int g_xg_done[64];     // per xg m-tile: # of completed n-tiles (16)
__device__ int g_cvtw;            // completed lin_W cvt tiles (target 125)
__device__ int g_prog;
__device__ int g_tile;

// ---------------- helpers ---------------------------------------------------
__device__ __forceinline__ void mma16(float* d, const uint32_t* a, const uint32_t* b) {
    asm volatile(
        "mma.sync.aligned.m16n8k16.row.col.f32.f16.f16.f32 "
        "{%0,%1,%2,%3}, {%4,%5,%6,%7}, {%8,%9}, {%0,%1,%2,%3};"
        : "+f"(d[0]), "+f"(d[1]), "+f"(d[2]), "+f"(d[3])
        : "r"(a[0]), "r"(a[1]), "r"(a[2]), "r"(a[3]), "r"(b[0]), "r"(b[1]));
}

__device__ __forceinline__ void ldm_x4(uint32_t* d, uint32_t addr) {
    asm volatile("ldmatrix.sync.aligned.m8n8.x4.shared.b16 {%0,%1,%2,%3}, [%4];"
        : "=r"(d[0]), "=r"(d[1]), "=r"(d[2]), "=r"(d[3]) : "r"(addr));
}
__device__ __forceinline__ void ldm_x2(uint32_t* d, uint32_t addr) {
    asm volatile("ldmatrix.sync.aligned.m8n8.x2.shared.b16 {%0,%1}, [%2];"
        : "=r"(d[0]), "=r"(d[1]) : "r"(addr));
}

__device__ __forceinline__ float sigmoidf_(float x) {
    return 1.0f / (1.0f + __expf(-x));
}

__device__ __forceinline__ void cp16(uint32_t dst, const void* src) {
    asm volatile("cp.async.cg.shared.global [%0], [%1], 16;" :: "r"(dst), "l"(src));
}
__device__ __forceinline__ void cp_commit() {
    asm volatile("cp.async.commit_group;");
}
template <int N>
__device__ __forceinline__ void cp_wait() {
    asm volatile("cp.async.wait_group %0;" :: "n"(N));
}

// XOR-swizzled smem byte offset for row r, half-offset ho within the row.
__device__ __forceinline__ uint32_t swz(uint32_t r, uint32_t ho, uint32_t rowbytes) {
    uint32_t b = ho << 1;
    uint32_t grp = b & ~127u;
    uint32_t ci = (b >> 4) & 7u;
    return r * rowbytes + grp + (((ci ^ (r & 7u)) << 4) | (b & 15u));
}

// ---------------- fused prep: transposes + init + emb cvt --------------------
// blocks [0,2048): W_ih transpose tiles; [2048,6144): W_hh transpose tiles;
// [6144,6400): init; [6400,10496): emb cvt grid-stride.
__global__ void prep_k(const float* __restrict__ W_ih, const float* __restrict__ W_hh,
                       const float* __restrict__ emb, const float* __restrict__ c0,
                       const float* __restrict__ h0)
{
    const int b = blockIdx.x, tid = threadIdx.x;
    if (b < 6144) {
        __shared__ float tmp[32][33];
        const float* in; __half* outp; int R, C, bx, by;
        if (b < 2048) { in = W_ih; outp = g_WihTh; R = EMB; C = G4; bx = b & 127; by = b >> 7; }
        else { int bb = b - 2048; in = W_hh; outp = g_WhhTh; R = HID; C = G4; bx = bb & 127; by = bb >> 7; }
        int cb = bx << 5, rb = by << 5;
        int x = tid & 31, y = tid >> 5;
#pragma unroll
        for (int i = 0; i < 32; i += 8)
            tmp[y + i][x] = in[(size_t)(rb + y + i) * C + cb + x];
        __syncthreads();
#pragma unroll
        for (int i = 0; i < 32; i += 8)
            outp[(size_t)(cb + y + i) * R + rb + x] = __float2half_rn(tmp[x][y + i]);
    } else if (b < 6400) {
        int i = (b - 6144) * 256 + tid;   // 0..65535 == BATCH*HID
        g_c[i] = c0[i];
        g_h0h[i] = __float2half_rn(h0[i]);
        if (i < SEQL) g_bar[i] = 0;
        if (i < 64) g_xg_done[i] = 0;
        if (i == 0) { g_prog = 0; g_tile = 0; g_cvtw = 0; }
    } else {
        const int n4 = VOCAB * EMB / 4;
        for (int i = (b - 6400) * 256 + tid; i < n4; i += 4096 * 256) {
            float4 v = *(const float4*)(emb + (size_t)i * 4);
            __half2* o = (__half2*)(g_embh + (size_t)i * 4);
            o[0] = __floats2half2_rn(v.x, v.y);
            o[1] = __floats2half2_rn(v.z, v.w);
        }
    }
}

// ---------------- MEGA kernel ------------------------------------------------
// Blocks 0..63: LSTM recurrence (W_hh slice resident in smem), step t gated on
// xg availability (g_xg_done), publishes g_prog; at t=127 writes h_T/c_T to
// out directly. Then join tile pool.
// Pool ids: [0,64) p1 mt0..3 | [64,189) lin_W cvt | [189,1149) rest of p1 |
// [1149,9149) p3 logits tiles gated on g_prog >= 2mt+2 and g_cvtw == 125.
// Pool GEMM: BM=128, BN=256, BK=64, 512 thr, 4-stage cp.async, 1 sync/chunk.
#define LW_B    131072            // 64 rows x 2048 B
#define LA_B    32768             // h stage: 64 rows x 512 B
#define MG_ASTG 16384
#define MG_BSTG 32768
#define MG_STG  (MG_ASTG + MG_BSTG)
#define MEGA_SMEM (LW_B + 2 * LA_B + 64 * 68 * 4)   // 214016 B (>= 4*MG_STG)

// One BM=128 x BN=256 tile, K=Kd (multiple of 64). A rows via sidx gather.
// Both A and B have leading dim = Kd. HALF_OUT selects fp16 vs fp32 C.
// Entry __syncthreads: makes fresh sidx visible to all 512 threads AND
// separates this tile's stage-0 writes from the previous tile's last reads.
template <bool HALF_OUT>
__device__ __forceinline__ void pool_tile(
    uint32_t sb, const __half* __restrict__ A, const __half* __restrict__ Bm,
    void* __restrict__ Cv, const float* __restrict__ bias,
    int n0, int Kd, int ldc, int m0out, const int* sidx)
{
    __syncthreads();

    const int tid = threadIdx.x, lane = tid & 31, wid = tid >> 5;
    const int mm = lane >> 3, r8 = lane & 7;
    const int wm = (wid & 1) << 6;
    const int wn = (wid >> 1) << 5;
    const int NCH = Kd >> 6;

    auto load_stage = [&](int st, int kt) {
        uint32_t stb = sb + (uint32_t)st * MG_STG;
#pragma unroll
        for (int i = 0; i < 2; i++) {
            int l = tid + (i << 9);
            int r = l >> 3, c8 = (l & 7) << 3;
            cp16(stb + swz(r, c8, 128), A + (size_t)sidx[r] * Kd + kt + c8);
        }
#pragma unroll
        for (int i = 0; i < 4; i++) {
            int l = tid + (i << 9);
            int r = l >> 3, c8 = (l & 7) << 3;
            cp16(stb + MG_ASTG + swz(r, c8, 128), Bm + (size_t)(n0 + r) * Kd + kt + c8);
        }
    };

    float acc[4][4][4];
#pragma unroll
    for (int i = 0; i < 4; i++)
#pragma unroll
        for (int j = 0; j < 4; j++)
#pragma unroll
            for (int q = 0; q < 4; q++) acc[i][j][q] = 0.f;

    load_stage(0, 0); cp_commit();
    load_stage(1, 64); cp_commit();

    for (int it = 0; it < NCH; it++) {
        if (it + 2 < NCH) load_stage((it + 2) & 3, (it + 2) << 6);
        cp_commit();
        cp_wait<2>();
        __syncthreads();

        uint32_t Ab = sb + (uint32_t)(it & 3) * MG_STG;
        uint32_t Bb = Ab + MG_ASTG;
#pragma unroll
        for (int ks = 0; ks < 4; ks++) {
            uint32_t af[4][4], bf[4][2];
#pragma unroll
            for (int fm = 0; fm < 4; fm++) {
                int row = wm + (fm << 4) + r8 + ((mm & 1) << 3);
                int ko = (ks << 4) + ((mm >> 1) << 3);
                ldm_x4(af[fm], Ab + swz(row, ko, 128));
            }
#pragma unroll
            for (int h = 0; h < 2; h++) {
                uint32_t t4[4];
                int col = wn + (h << 4) + ((mm >> 1) << 3) + r8;
                int ko = (ks << 4) + ((mm & 1) << 3);
                ldm_x4(t4, Bb + swz(col, ko, 128));
                bf[h * 2][0] = t4[0]; bf[h * 2][1] = t4[1];
                bf[h * 2 + 1][0] = t4[2]; bf[h * 2 + 1][1] = t4[3];
            }
#pragma unroll
            for (int fm = 0; fm < 4; fm++)
#pragma unroll
                for (int fn = 0; fn < 4; fn++)
                    mma16(acc[fm][fn], af[fm], bf[fn]);
        }
    }

    const int c2 = (lane & 3) << 1;
#pragma unroll
    for (int fm = 0; fm < 4; fm++) {
        int r = m0out + wm + (fm << 4) + (lane >> 2);
#pragma unroll
        for (int fn = 0; fn < 4; fn++) {
            int c = n0 + wn + (fn << 3) + c2;
            float b0 = bias[c], b1 = bias[c + 1];
            if (HALF_OUT) {
                __half* C = (__half*)Cv;
                *(__half2*)(C + (size_t)r * ldc + c) =
                    __floats2half2_rn(acc[fm][fn][0] + b0, acc[fm][fn][1] + b1);
                *(__half2*)(C + (size_t)(r + 8) * ldc + c) =
                    __floats2half2_rn(acc[fm][fn][2] + b0, acc[fm][fn][3] + b1);
            } else {
                float* C = (float*)Cv;
                float2 v0 = make_float2(acc[fm][fn][0] + b0, acc[fm][fn][1] + b1);
                float2 v1 = make_float2(acc[fm][fn][2] + b0, acc[fm][fn][3] + b1);
                *(float2*)(C + (size_t)r * ldc + c) = v0;
                *(float2*)(C + (size_t)(r + 8) * ldc + c) = v1;
            }
        }
    }
}

__global__ __launch_bounds__(512, 1)
void mega_k(float* __restrict__ out, const float* __restrict__ lin_b,
            const float* __restrict__ b_lstm, const int* __restrict__ input,
            const float* __restrict__ lin_W)
{
    extern __shared__ char smem[];
    const uint32_t sb = (uint32_t)__cvta_generic_to_shared(smem);
    const int tid = threadIdx.x, lane = tid & 31, wid = tid >> 5;
    const int mm = lane >> 3, r8 = lane & 7;
    __shared__ int s_id;
    __shared__ int sidx[128];

    if (blockIdx.x < 64) {
        // ================= LSTM role =================
        const uint32_t bwb = sb, ab = sb + LW_B;
        float* Gs = (float*)(smem + LW_B + 2 * LA_B);
        const int u0 = (int)blockIdx.x << 4;      // 16 units
        const int wc = (wid & 7) << 3;
        const int ksb = (wid >> 3) << 3;
        const int sel = mm & 1;

        for (int idx = tid; idx < 64 * 128; idx += 512) {
            int r = idx >> 7, c8 = (idx & 127) << 3;
            int grow = ((r >> 4) << 10) + u0 + (r & 15);
            cp16(bwb + swz(r, c8, 2048), g_WhhTh + (size_t)grow * HID + c8);
        }
        cp_commit(); cp_wait<0>();
        __syncthreads();

        for (int t = 0; t < SEQL; t++) {
            // wait for xg rows of this timestep (phase-1 pool tiles)
            if (tid == 0) {
                while (*(volatile int*)&g_xg_done[t >> 1] < 16) __nanosleep(64);
            }
            __syncthreads();
            __threadfence();

            const __half* hp = t ? (g_hidh + (size_t)(t - 1) * BATCH * HID) : g_h0h;
            float acc[4][4];
#pragma unroll
            for (int i = 0; i < 4; i++)
#pragma unroll
                for (int q = 0; q < 4; q++) acc[i][q] = 0.f;

            auto loadA = [&](int st, int kc) {
#pragma unroll
                for (int i = 0; i < 4; i++) {
                    int l = tid + (i << 9);
                    int r = l >> 5, c8 = (l & 31) << 3;
                    cp16(ab + (uint32_t)st * LA_B + swz(r, c8, 512),
                         hp + (size_t)r * HID + kc + c8);
                }
            };

            loadA(0, 0); cp_commit();
            for (int ch = 0; ch < 4; ch++) {
                if (ch < 3) { loadA((ch + 1) & 1, (ch + 1) << 8); cp_commit(); cp_wait<1>(); }
                else         cp_wait<0>();
                __syncthreads();
                uint32_t Ab = ab + (uint32_t)(ch & 1) * LA_B;
                const int kb = ch << 8;
#pragma unroll
                for (int ks = 0; ks < 8; ks++) {
                    const int kk = ksb + ks;
                    uint32_t af[4][4], bf[2];
#pragma unroll
                    for (int fm = 0; fm < 4; fm++) {
                        int row = (fm << 4) + r8 + ((mm & 1) << 3);
                        int ko = (kk << 4) + ((mm >> 1) << 3);
                        ldm_x4(af[fm], Ab + swz(row, ko, 512));
                    }
                    ldm_x2(bf, bwb + swz(wc + r8, kb + (kk << 4) + (sel << 3), 2048));
#pragma unroll
                    for (int fm = 0; fm < 4; fm++) mma16(acc[fm], af[fm], bf);
                }
                __syncthreads();
            }

            const int c2l = (lane & 3) << 1;
            if (wid < 8) {
#pragma unroll
                for (int fm = 0; fm < 4; fm++) {
                    int r = (fm << 4) + (lane >> 2), c = wc + c2l;
                    Gs[r * 68 + c]           = acc[fm][0];
                    Gs[r * 68 + c + 1]       = acc[fm][1];
                    Gs[(r + 8) * 68 + c]     = acc[fm][2];
                    Gs[(r + 8) * 68 + c + 1] = acc[fm][3];
                }
            }
            __syncthreads();
            if (wid >= 8) {
#pragma unroll
                for (int fm = 0; fm < 4; fm++) {
                    int r = (fm << 4) + (lane >> 2), c = wc + c2l;
                    Gs[r * 68 + c]           += acc[fm][0];
                    Gs[r * 68 + c + 1]       += acc[fm][1];
                    Gs[(r + 8) * 68 + c]     += acc[fm][2];
                    Gs[(r + 8) * 68 + c + 1] += acc[fm][3];
                }
            }
            __syncthreads();

#pragma unroll
            for (int i = 0; i < 2; i++) {
                int p = tid + (i << 9);
                int row = p >> 4, u = p & 15;
                size_t xb = ((size_t)(t * BATCH + row)) * G4 + u0 + u;
                float gi = Gs[row * 68 + u]      + __half2float(g_xgh[xb]);
                float gf = Gs[row * 68 + 16 + u] + __half2float(g_xgh[xb + HID]);
                float gg = Gs[row * 68 + 32 + u] + __half2float(g_xgh[xb + 2 * HID]);
                float go = Gs[row * 68 + 48 + u] + __half2float(g_xgh[xb + 3 * HID]);
                float iv = sigmoidf_(gi);
                float fv = sigmoidf_(gf);
                float gv = tanhf(gg);
                float ov = sigmoidf_(go);
                int ci = row * HID + u0 + u;
                float cv = fv * g_c[ci] + iv * gv;
                g_c[ci] = cv;
                float hv = ov * tanhf(cv);
                g_hidh[(size_t)(t * BATCH + row) * HID + u0 + u] = __float2half_rn(hv);
                if (t == SEQL - 1) {
                    const size_t LOG = (size_t)MTOT * VOCAB;
                    out[LOG + ci] = hv;                       // h_T (full fp32)
                    out[LOG + (size_t)BATCH * HID + ci] = cv; // c_T
                }
            }

            __threadfence();
            __syncthreads();
            if (tid == 0) {
                atomicAdd(&g_bar[t], 1);
                while (*(volatile int*)&g_bar[t] < 64) __nanosleep(32);
                if (blockIdx.x == 0) atomicExch(&g_prog, t + 1);
            }
            __syncthreads();
        }
        __syncthreads();
    }

    // ================= tile pool role =================
    for (;;) {
        if (tid == 0) s_id = atomicAdd(&g_tile, 1);
        __syncthreads();
        const int id = s_id;
        if (id >= NTILE) break;

        if (id < NT1A || (id >= NT1A + NCVW && id < NT1 + NCVW)) {
            // phase-1: xg tile. mt-major so rows finish in order.
            const int p1id = (id < NT1A) ? id : (id - NCVW);
            const int mt = p1id >> 4, nt = p1id & 15;
            const int m0 = mt << 7, n0 = nt << 8;
            if (tid < 128) sidx[tid] = input[m0 + tid];
            pool_tile<true>(sb, g_embh, g_WihTh, g_xgh, b_lstm, n0, EMB, G4, m0, sidx);
            __threadfence();
            __syncthreads();
            if (tid == 0) atomicAdd(&g_xg_done[mt], 1);
        } else if (id < NT1A + NCVW) {
            // lin_W fp32 -> fp16 convert tile (256 rows)
            const int c = id - NT1A;
            const float* src = lin_W + (size_t)c * 256 * HID;
            __half* dst = g_linWh + (size_t)c * 256 * HID;
            for (int i = tid; i < 256 * HID / 4; i += 512) {
                float4 v = *(const float4*)(src + (size_t)i * 4);
                __half2* o = (__half2*)(dst + (size_t)i * 4);
                o[0] = __floats2half2_rn(v.x, v.y);
                o[1] = __floats2half2_rn(v.z, v.w);
            }
            __threadfence();
            __syncthreads();
            if (tid == 0) atomicAdd(&g_cvtw, 1);
        } else {
            // phase-3: logits tile, gated on LSTM progress + lin_W cvt done.
            const int id3 = id - NT1 - NCVW;
            const int mt = id3 / NT_N, nt = id3 - mt * NT_N;
            const int m0 = mt << 7, n0 = nt << 8;
            if (tid == 0) {
                while (*(volatile int*)&g_prog < 2 * mt + 2 ||
                       *(volatile int*)&g_cvtw < NCVW) __nanosleep(128);
            }
            __syncthreads();
            __threadfence();
            if (tid < 128) sidx[tid] = m0 + tid;
            pool_tile<false>(sb, g_hidh, g_linWh, out, lin_b, n0, HID, VOCAB, m0, sidx);
            __syncthreads();
        }
    }
}

// ---------------- launch -----------------------------------------------------
extern "C" void kernel_launch(void* const* d_in, const int* in_sizes, int n_in,
                              void* d_out, int out_size)
{
    const int*   input  = (const int*)d_in[0];
    const float* emb    = (const float*)d_in[1];
    const float* W_ih   = (const float*)d_in[2];
    const float* W_hh   = (const float*)d_in[3];
    const float* b_lstm = (const float*)d_in[4];
    const float* lin_W  = (const float*)d_in[5];
    const float* lin_b  = (const float*)d_in[6];
    const float* h0     = (const float*)d_in[7];
    const float* c0     = (const float*)d_in[8];
    float* out = (float*)d_out;

    int nsm = 148;
    cudaDeviceGetAttribute(&nsm, cudaDevAttrMultiProcessorCount, 0);
    if (nsm < 66) nsm = 66;   // need >64 resident blocks for pool progress

    cudaFuncSetAttribute(mega_k, cudaFuncAttributeMaxDynamicSharedMemorySize, MEGA_SMEM);

    // One fused prep launch: W transposes + init + emb cvt
    prep_k<<<10496, 256>>>(W_ih, W_hh, emb, c0, h0);

    // Fused: phase-1 pool + lin_W cvt + LSTM recurrence + phase-3 pool + tail
    mega_k<<<nsm, 512, MEGA_SMEM>>>(out, lin_b, b_lstm, input, lin_W);
}

// round 17
// speedup vs baseline: 5.0914x; 1.0087x over previous
#include <cuda_runtime.h>
#include <cuda_fp16.h>
#include <cstdint>

#define SEQL  128
#define BATCH 64
#define EMB   512
#define HID   1024
#define VOCAB 32000
#define G4    4096      // 4*HID
#define MTOT  8192      // SEQL*BATCH
#define NT_N  250       // 32000 / 128
#define NT1   2048      // phase-1 tiles: 64 mt x 32 nt (BM=128, BN=128)
#define NT1A  128       // first p1 batch (mt 0..3) before cvtW tiles
#define NCVW  125       // lin_W convert tiles (256 rows each)
#define NTILE (NT1 + NCVW + 64 * NT_N)   // 18173

// ---------------- scratch (device globals) ----------------------------------
__device__ __align__(128) __half g_xgh[(size_t)MTOT * G4];     // 67 MB fp16
__device__ __align__(128) __half g_hidh[(size_t)MTOT * HID];   // 16 MB
__device__ __align__(128) __half g_embh[(size_t)VOCAB * EMB];  // 32 MB
__device__ __align__(128) __half g_linWh[(size_t)VOCAB * HID]; // 65 MB
__device__ __align__(128) __half g_WihTh[(size_t)G4 * EMB];    // 4 MB
__device__ __align__(128) __half g_WhhTh[(size_t)G4 * HID];    // 8 MB
__device__ __align__(128) __half g_h0h[BATCH * HID];
__device__ __align__(128) float  g_c[BATCH * HID];
__device__ int g_bar[SEQL];
__device__ int g_xg_done[64];     // per xg m-tile: # of completed n-tiles (32)
__device__ int g_cvtw;            // completed lin_W cvt tiles (target 125)
__device__ int g_prog;
__device__ int g_tile;

// ---------------- helpers ---------------------------------------------------
__device__ __forceinline__ void mma16(float* d, const uint32_t* a, const uint32_t* b) {
    asm volatile(
        "mma.sync.aligned.m16n8k16.row.col.f32.f16.f16.f32 "
        "{%0,%1,%2,%3}, {%4,%5,%6,%7}, {%8,%9}, {%0,%1,%2,%3};"
        : "+f"(d[0]), "+f"(d[1]), "+f"(d[2]), "+f"(d[3])
        : "r"(a[0]), "r"(a[1]), "r"(a[2]), "r"(a[3]), "r"(b[0]), "r"(b[1]));
}

__device__ __forceinline__ void ldm_x4(uint32_t* d, uint32_t addr) {
    asm volatile("ldmatrix.sync.aligned.m8n8.x4.shared.b16 {%0,%1,%2,%3}, [%4];"
        : "=r"(d[0]), "=r"(d[1]), "=r"(d[2]), "=r"(d[3]) : "r"(addr));
}
__device__ __forceinline__ void ldm_x2(uint32_t* d, uint32_t addr) {
    asm volatile("ldmatrix.sync.aligned.m8n8.x2.shared.b16 {%0,%1}, [%2];"
        : "=r"(d[0]), "=r"(d[1]) : "r"(addr));
}

__device__ __forceinline__ float sigmoidf_(float x) {
    return 1.0f / (1.0f + __expf(-x));
}

__device__ __forceinline__ void cp16(uint32_t dst, const void* src) {
    asm volatile("cp.async.cg.shared.global [%0], [%1], 16;" :: "r"(dst), "l"(src));
}
__device__ __forceinline__ void cp_commit() {
    asm volatile("cp.async.commit_group;");
}
template <int N>
__device__ __forceinline__ void cp_wait() {
    asm volatile("cp.async.wait_group %0;" :: "n"(N));
}

// group barrier: 256 threads, named barrier id (1 or 2)
__device__ __forceinline__ void barg(int id) {
    asm volatile("bar.sync %0, 256;" :: "r"(id) : "memory");
}

// XOR-swizzled smem byte offset for row r, half-offset ho within the row.
__device__ __forceinline__ uint32_t swz(uint32_t r, uint32_t ho, uint32_t rowbytes) {
    uint32_t b = ho << 1;
    uint32_t grp = b & ~127u;
    uint32_t ci = (b >> 4) & 7u;
    return r * rowbytes + grp + (((ci ^ (r & 7u)) << 4) | (b & 15u));
}

// ---------------- fused prep: transposes + init + emb cvt --------------------
__global__ void prep_k(const float* __restrict__ W_ih, const float* __restrict__ W_hh,
                       const float* __restrict__ emb, const float* __restrict__ c0,
                       const float* __restrict__ h0)
{
    const int b = blockIdx.x, tid = threadIdx.x;
    if (b < 6144) {
        __shared__ float tmp[32][33];
        const float* in; __half* outp; int R, C, bx, by;
        if (b < 2048) { in = W_ih; outp = g_WihTh; R = EMB; C = G4; bx = b & 127; by = b >> 7; }
        else { int bb = b - 2048; in = W_hh; outp = g_WhhTh; R = HID; C = G4; bx = bb & 127; by = bb >> 7; }
        int cb = bx << 5, rb = by << 5;
        int x = tid & 31, y = tid >> 5;
#pragma unroll
        for (int i = 0; i < 32; i += 8)
            tmp[y + i][x] = in[(size_t)(rb + y + i) * C + cb + x];
        __syncthreads();
#pragma unroll
        for (int i = 0; i < 32; i += 8)
            outp[(size_t)(cb + y + i) * R + rb + x] = __float2half_rn(tmp[x][y + i]);
    } else if (b < 6400) {
        int i = (b - 6144) * 256 + tid;   // 0..65535 == BATCH*HID
        g_c[i] = c0[i];
        g_h0h[i] = __float2half_rn(h0[i]);
        if (i < SEQL) g_bar[i] = 0;
        if (i < 64) g_xg_done[i] = 0;
        if (i == 0) { g_prog = 0; g_tile = 0; g_cvtw = 0; }
    } else {
        const int n4 = VOCAB * EMB / 4;
        for (int i = (b - 6400) * 256 + tid; i < n4; i += 4096 * 256) {
            float4 v = *(const float4*)(emb + (size_t)i * 4);
            __half2* o = (__half2*)(g_embh + (size_t)i * 4);
            o[0] = __floats2half2_rn(v.x, v.y);
            o[1] = __floats2half2_rn(v.z, v.w);
        }
    }
}

// ---------------- MEGA kernel ------------------------------------------------
// Blocks 0..63: LSTM recurrence first (full-block syncthreads), then pool.
// Pool role: block splits into TWO independent 256-thread groups (warps 0-7 /
// 8-15). Each group: own tile stream, own 3x32KB stage ring at sb + g*96KB,
// named barrier (1+g). Tiles BM=128, BN=128, BK=64.
// Chunk loop order is wait -> barrier -> compute -> prefetch(it+2) -> commit:
// the prefetch that overwrites stage (it-1)%3 is issued only after the
// barrier proving all iter-(it-1) reads finished (3-stage ring safety).
// Pool ids: [0,128) p1 mt0..3 | [128,253) lin_W cvt | [253,2173) rest of p1 |
// [2173,18173) p3 logits tiles gated on g_prog >= 2mt+2 and g_cvtw == 125.
#define LW_B    131072            // LSTM W slice: 64 rows x 2048 B
#define LA_B    32768             // LSTM h stage: 64 rows x 512 B
#define PG_STG  32768             // pool stage: A 16KB + B 16KB
#define PG_GRP  (3 * PG_STG)      // 98304 B per group
#define MEGA_SMEM (LW_B + 2 * LA_B + 64 * 68 * 4)   // 214016 B (>= 2*PG_GRP)

template <bool HALF_OUT>
__device__ __forceinline__ void pool_tile(
    uint32_t gb, int bid, const __half* __restrict__ A,
    const __half* __restrict__ Bm, void* __restrict__ Cv,
    const float* __restrict__ bias,
    int n0, int Kd, int ldc, int m0out, const int* sidx)
{
    barg(bid);   // sidx visible; prior tile's last reads done before stage-0 write

    const int gtid = threadIdx.x & 255;
    const int lane = gtid & 31, wid = gtid >> 5;
    const int mm = lane >> 3, r8 = lane & 7;
    const int wm = (wid & 1) << 6;     // 0 / 64
    const int wn = (wid >> 1) << 5;    // 0..96
    const int NCH = Kd >> 6;

    auto load_stage = [&](int st, int kt) {
        uint32_t stb = gb + (uint32_t)st * PG_STG;
#pragma unroll
        for (int i = 0; i < 4; i++) {
            int l = gtid + (i << 8);
            int r = l >> 3, c8 = (l & 7) << 3;
            cp16(stb + swz(r, c8, 128), A + (size_t)sidx[r] * Kd + kt + c8);
        }
#pragma unroll
        for (int i = 0; i < 4; i++) {
            int l = gtid + (i << 8);
            int r = l >> 3, c8 = (l & 7) << 3;
            cp16(stb + 16384 + swz(r, c8, 128), Bm + (size_t)(n0 + r) * Kd + kt + c8);
        }
    };

    float acc[4][4][4];
#pragma unroll
    for (int i = 0; i < 4; i++)
#pragma unroll
        for (int j = 0; j < 4; j++)
#pragma unroll
            for (int q = 0; q < 4; q++) acc[i][j][q] = 0.f;

    load_stage(0, 0); cp_commit();
    load_stage(1, 64); cp_commit();

    for (int it = 0; it < NCH; it++) {
        cp_wait<1>();      // all but newest group done => stage it resident
        barg(bid);         // all threads finished reading stage (it-1)%3

        uint32_t Ab = gb + (uint32_t)(it % 3) * PG_STG;
        uint32_t Bb = Ab + 16384;
#pragma unroll
        for (int ks = 0; ks < 4; ks++) {
            uint32_t af[4][4], bf[4][2];
#pragma unroll
            for (int fm = 0; fm < 4; fm++) {
                int row = wm + (fm << 4) + r8 + ((mm & 1) << 3);
                int ko = (ks << 4) + ((mm >> 1) << 3);
                ldm_x4(af[fm], Ab + swz(row, ko, 128));
            }
#pragma unroll
            for (int h = 0; h < 2; h++) {
                uint32_t t4[4];
                int col = wn + (h << 4) + ((mm >> 1) << 3) + r8;
                int ko = (ks << 4) + ((mm & 1) << 3);
                ldm_x4(t4, Bb + swz(col, ko, 128));
                bf[h * 2][0] = t4[0]; bf[h * 2][1] = t4[1];
                bf[h * 2 + 1][0] = t4[2]; bf[h * 2 + 1][1] = t4[3];
            }
#pragma unroll
            for (int fm = 0; fm < 4; fm++)
#pragma unroll
                for (int fn = 0; fn < 4; fn++)
                    mma16(acc[fm][fn], af[fm], bf[fn]);
        }

        // prefetch AFTER the barrier: overwrites stage (it-1)%3 safely
        if (it + 2 < NCH) load_stage((it + 2) % 3, (it + 2) << 6);
        cp_commit();
    }

    const int c2 = (lane & 3) << 1;
#pragma unroll
    for (int fm = 0; fm < 4; fm++) {
        int r = m0out + wm + (fm << 4) + (lane >> 2);
#pragma unroll
        for (int fn = 0; fn < 4; fn++) {
            int c = n0 + wn + (fn << 3) + c2;
            float b0 = bias[c], b1 = bias[c + 1];
            if (HALF_OUT) {
                __half* C = (__half*)Cv;
                *(__half2*)(C + (size_t)r * ldc + c) =
                    __floats2half2_rn(acc[fm][fn][0] + b0, acc[fm][fn][1] + b1);
                *(__half2*)(C + (size_t)(r + 8) * ldc + c) =
                    __floats2half2_rn(acc[fm][fn][2] + b0, acc[fm][fn][3] + b1);
            } else {
                float* C = (float*)Cv;
                float2 v0 = make_float2(acc[fm][fn][0] + b0, acc[fm][fn][1] + b1);
                float2 v1 = make_float2(acc[fm][fn][2] + b0, acc[fm][fn][3] + b1);
                *(float2*)(C + (size_t)r * ldc + c) = v0;
                *(float2*)(C + (size_t)(r + 8) * ldc + c) = v1;
            }
        }
    }
}

__global__ __launch_bounds__(512, 1)
void mega_k(float* __restrict__ out, const float* __restrict__ lin_b,
            const float* __restrict__ b_lstm, const int* __restrict__ input,
            const float* __restrict__ lin_W)
{
    extern __shared__ char smem[];
    const uint32_t sb = (uint32_t)__cvta_generic_to_shared(smem);
    const int tid = threadIdx.x, lane = tid & 31, wid = tid >> 5;
    const int mm = lane >> 3, r8 = lane & 7;
    __shared__ int s_id2[2];
    __shared__ int sidx2[2][128];

    if (blockIdx.x < 64) {
        // ================= LSTM role (full block, 512 threads) =================
        const uint32_t bwb = sb, ab = sb + LW_B;
        float* Gs = (float*)(smem + LW_B + 2 * LA_B);
        const int u0 = (int)blockIdx.x << 4;      // 16 units
        const int wc = (wid & 7) << 3;
        const int ksb = (wid >> 3) << 3;
        const int sel = mm & 1;

        for (int idx = tid; idx < 64 * 128; idx += 512) {
            int r = idx >> 7, c8 = (idx & 127) << 3;
            int grow = ((r >> 4) << 10) + u0 + (r & 15);
            cp16(bwb + swz(r, c8, 2048), g_WhhTh + (size_t)grow * HID + c8);
        }
        cp_commit(); cp_wait<0>();
        __syncthreads();

        for (int t = 0; t < SEQL; t++) {
            if (tid == 0) {
                while (*(volatile int*)&g_xg_done[t >> 1] < 32) __nanosleep(64);
            }
            __syncthreads();
            __threadfence();

            const __half* hp = t ? (g_hidh + (size_t)(t - 1) * BATCH * HID) : g_h0h;
            float acc[4][4];
#pragma unroll
            for (int i = 0; i < 4; i++)
#pragma unroll
                for (int q = 0; q < 4; q++) acc[i][q] = 0.f;

            auto loadA = [&](int st, int kc) {
#pragma unroll
                for (int i = 0; i < 4; i++) {
                    int l = tid + (i << 9);
                    int r = l >> 5, c8 = (l & 31) << 3;
                    cp16(ab + (uint32_t)st * LA_B + swz(r, c8, 512),
                         hp + (size_t)r * HID + kc + c8);
                }
            };

            loadA(0, 0); cp_commit();
            for (int ch = 0; ch < 4; ch++) {
                if (ch < 3) { loadA((ch + 1) & 1, (ch + 1) << 8); cp_commit(); cp_wait<1>(); }
                else         cp_wait<0>();
                __syncthreads();
                uint32_t Ab = ab + (uint32_t)(ch & 1) * LA_B;
                const int kb = ch << 8;
#pragma unroll
                for (int ks = 0; ks < 8; ks++) {
                    const int kk = ksb + ks;
                    uint32_t af[4][4], bf[2];
#pragma unroll
                    for (int fm = 0; fm < 4; fm++) {
                        int row = (fm << 4) + r8 + ((mm & 1) << 3);
                        int ko = (kk << 4) + ((mm >> 1) << 3);
                        ldm_x4(af[fm], Ab + swz(row, ko, 512));
                    }
                    ldm_x2(bf, bwb + swz(wc + r8, kb + (kk << 4) + (sel << 3), 2048));
#pragma unroll
                    for (int fm = 0; fm < 4; fm++) mma16(acc[fm], af[fm], bf);
                }
                __syncthreads();
            }

            const int c2l = (lane & 3) << 1;
            if (wid < 8) {
#pragma unroll
                for (int fm = 0; fm < 4; fm++) {
                    int r = (fm << 4) + (lane >> 2), c = wc + c2l;
                    Gs[r * 68 + c]           = acc[fm][0];
                    Gs[r * 68 + c + 1]       = acc[fm][1];
                    Gs[(r + 8) * 68 + c]     = acc[fm][2];
                    Gs[(r + 8) * 68 + c + 1] = acc[fm][3];
                }
            }
            __syncthreads();
            if (wid >= 8) {
#pragma unroll
                for (int fm = 0; fm < 4; fm++) {
                    int r = (fm << 4) + (lane >> 2), c = wc + c2l;
                    Gs[r * 68 + c]           += acc[fm][0];
                    Gs[r * 68 + c + 1]       += acc[fm][1];
                    Gs[(r + 8) * 68 + c]     += acc[fm][2];
                    Gs[(r + 8) * 68 + c + 1] += acc[fm][3];
                }
            }
            __syncthreads();

#pragma unroll
            for (int i = 0; i < 2; i++) {
                int p = tid + (i << 9);
                int row = p >> 4, u = p & 15;
                size_t xb = ((size_t)(t * BATCH + row)) * G4 + u0 + u;
                float gi = Gs[row * 68 + u]      + __half2float(g_xgh[xb]);
                float gf = Gs[row * 68 + 16 + u] + __half2float(g_xgh[xb + HID]);
                float gg = Gs[row * 68 + 32 + u] + __half2float(g_xgh[xb + 2 * HID]);
                float go = Gs[row * 68 + 48 + u] + __half2float(g_xgh[xb + 3 * HID]);
                float iv = sigmoidf_(gi);
                float fv = sigmoidf_(gf);
                float gv = tanhf(gg);
                float ov = sigmoidf_(go);
                int ci = row * HID + u0 + u;
                float cv = fv * g_c[ci] + iv * gv;
                g_c[ci] = cv;
                float hv = ov * tanhf(cv);
                g_hidh[(size_t)(t * BATCH + row) * HID + u0 + u] = __float2half_rn(hv);
                if (t == SEQL - 1) {
                    const size_t LOG = (size_t)MTOT * VOCAB;
                    out[LOG + ci] = hv;                       // h_T (full fp32)
                    out[LOG + (size_t)BATCH * HID + ci] = cv; // c_T
                }
            }

            __threadfence();
            __syncthreads();
            if (tid == 0) {
                atomicAdd(&g_bar[t], 1);
                while (*(volatile int*)&g_bar[t] < 64) __nanosleep(32);
                if (blockIdx.x == 0) atomicExch(&g_prog, t + 1);
            }
            __syncthreads();
        }
        __syncthreads();
    }

    // ================= tile pool role: two independent 256-thread groups ======
    {
        const int g = tid >> 8;            // group 0 / 1
        const int gtid = tid & 255;
        const int bid = 1 + g;             // named barrier id
        const uint32_t gb = sb + (uint32_t)g * PG_GRP;
        int* sidx = sidx2[g];

        for (;;) {
            if (gtid == 0) s_id2[g] = atomicAdd(&g_tile, 1);
            barg(bid);
            const int id = s_id2[g];
            if (id >= NTILE) break;

            if (id < NT1A || (id >= NT1A + NCVW && id < NT1 + NCVW)) {
                // phase-1: xg tile (BM=128, BN=128). mt-major, 32 nt per mt.
                const int p1id = (id < NT1A) ? id : (id - NCVW);
                const int mt = p1id >> 5, nt = p1id & 31;
                const int m0 = mt << 7, n0 = nt << 7;
                if (gtid < 128) sidx[gtid] = input[m0 + gtid];
                pool_tile<true>(gb, bid, g_embh, g_WihTh, g_xgh, b_lstm,
                                n0, EMB, G4, m0, sidx);
                __threadfence();
                barg(bid);
                if (gtid == 0) atomicAdd(&g_xg_done[mt], 1);
            } else if (id < NT1A + NCVW) {
                // lin_W fp32 -> fp16 convert tile (256 rows)
                const int c = id - NT1A;
                const float* src = lin_W + (size_t)c * 256 * HID;
                __half* dst = g_linWh + (size_t)c * 256 * HID;
                for (int i = gtid; i < 256 * HID / 4; i += 256) {
                    float4 v = *(const float4*)(src + (size_t)i * 4);
                    __half2* o = (__half2*)(dst + (size_t)i * 4);
                    o[0] = __floats2half2_rn(v.x, v.y);
                    o[1] = __floats2half2_rn(v.z, v.w);
                }
                __threadfence();
                barg(bid);
                if (gtid == 0) atomicAdd(&g_cvtw, 1);
            } else {
                // phase-3: logits tile, gated on LSTM progress + lin_W cvt.
                const int id3 = id - NT1 - NCVW;
                const int mt = id3 / NT_N, nt = id3 - mt * NT_N;
                const int m0 = mt << 7, n0 = nt << 7;
                if (gtid == 0) {
                    while (*(volatile int*)&g_prog < 2 * mt + 2 ||
                           *(volatile int*)&g_cvtw < NCVW) __nanosleep(128);
                }
                barg(bid);
                __threadfence();
                if (gtid < 128) sidx[gtid] = m0 + gtid;
                pool_tile<false>(gb, bid, g_hidh, g_linWh, out, lin_b,
                                 n0, HID, VOCAB, m0, sidx);
            }
        }
    }
}

// ---------------- launch -----------------------------------------------------
extern "C" void kernel_launch(void* const* d_in, const int* in_sizes, int n_in,
                              void* d_out, int out_size)
{
    const int*   input  = (const int*)d_in[0];
    const float* emb    = (const float*)d_in[1];
    const float* W_ih   = (const float*)d_in[2];
    const float* W_hh   = (const float*)d_in[3];
    const float* b_lstm = (const float*)d_in[4];
    const float* lin_W  = (const float*)d_in[5];
    const float* lin_b  = (const float*)d_in[6];
    const float* h0     = (const float*)d_in[7];
    const float* c0     = (const float*)d_in[8];
    float* out = (float*)d_out;

    int nsm = 148;
    cudaDeviceGetAttribute(&nsm, cudaDevAttrMultiProcessorCount, 0);
    if (nsm < 66) nsm = 66;   // need >64 resident blocks for pool progress

    cudaFuncSetAttribute(mega_k, cudaFuncAttributeMaxDynamicSharedMemorySize, MEGA_SMEM);

    // One fused prep launch: W transposes + init + emb cvt
    prep_k<<<10496, 256>>>(W_ih, W_hh, emb, c0, h0);

    // Fused: phase-1 pool + lin_W cvt + LSTM recurrence + phase-3 pool + tail
    mega_k<<<nsm, 512, MEGA_SMEM>>>(out, lin_b, b_lstm, input, lin_W);
}